// round 9
// baseline (speedup 1.0000x reference)
#include <cuda_runtime.h>
#include <cuda_bf16.h>
#include <cstdint>
#include <math.h>

#define NTOK 4096
#define EDIM 1024
#define HID  4096
#define NLAYER 12
#define NHEAD 16
#define HDIM 64
#define BATCH 2048
#define VOC  32000
#define QKVN 3072

typedef __nv_bfloat16 bf16;

// ---------------- scratch (device globals) ----------------
__device__ bf16 g_Wqkv_h[NLAYER * QKVN * EDIM];
__device__ bf16 g_Wqkv_l[NLAYER * QKVN * EDIM];
__device__ bf16 g_Wo_h [NLAYER * EDIM * EDIM];
__device__ bf16 g_Wo_l [NLAYER * EDIM * EDIM];
__device__ bf16 g_W1_h [NLAYER * HID * EDIM];
__device__ bf16 g_W1_l [NLAYER * HID * EDIM];
__device__ bf16 g_W2_h [NLAYER * EDIM * HID];
__device__ bf16 g_W2_l [NLAYER * EDIM * HID];
__device__ bf16 g_Ue_h [VOC * EDIM];
__device__ bf16 g_Ue_l [VOC * EDIM];
__device__ float g_X  [NTOK * EDIM];
__device__ float g_X2 [NTOK * EDIM];
__device__ bf16  g_Xh [NTOK * EDIM];
__device__ bf16  g_Xl [NTOK * EDIM];
__device__ bf16  g_X2h[NTOK * EDIM];
__device__ bf16  g_X2l[NTOK * EDIM];
__device__ bf16  g_QKVh[NTOK * QKVN];
__device__ bf16  g_QKVl[NTOK * QKVN];
__device__ bf16  g_Oh [NTOK * EDIM];
__device__ bf16  g_Ol [NTOK * EDIM];
__device__ bf16  g_H1h[NTOK * HID];
__device__ bf16  g_H1l[NTOK * HID];

__device__ __forceinline__ void split2(float v, bf16& h, bf16& l) {
    h = __float2bfloat16(v);
    l = __float2bfloat16(v - __bfloat162float(h));
}

// ---------------- weight transpose + split ----------------
__device__ __forceinline__ void tconv_tile(const float* __restrict__ src,
                                           bf16* __restrict__ dhi, bf16* __restrict__ dlo,
                                           int K, int N, int k0, int n0,
                                           float (*t)[33])
{
    const int tx = threadIdx.x, ty = threadIdx.y;
#pragma unroll
    for (int j = 0; j < 4; j++)
        t[ty + 8 * j][tx] = src[(size_t)(k0 + ty + 8 * j) * N + n0 + tx];
    __syncthreads();
#pragma unroll
    for (int j = 0; j < 4; j++) {
        float v = t[tx][ty + 8 * j];
        bf16 h, l; split2(v, h, l);
        size_t o = (size_t)(n0 + ty + 8 * j) * K + k0 + tx;
        dhi[o] = h; dlo[o] = l;
    }
}

__global__ void tconv_fused_kernel(const float* __restrict__ Wo,
                                   const float* __restrict__ W1,
                                   const float* __restrict__ W2,
                                   const float* __restrict__ Ue,
                                   bf16* Woh, bf16* Wol, bf16* W1h, bf16* W1l,
                                   bf16* W2h, bf16* W2l, bf16* Ueh, bf16* Uel)
{
    __shared__ float t[32][33];
    int id = blockIdx.x;
    if (id < 12288) {
        int l = id / 1024, r = id % 1024;
        size_t off = (size_t)l * EDIM * EDIM;
        tconv_tile(Wo + off, Woh + off, Wol + off, EDIM, EDIM,
                   (r / 32) * 32, (r % 32) * 32, t);
        return;
    }
    id -= 12288;
    if (id < 49152) {
        int l = id / 4096, r = id % 4096;
        size_t off = (size_t)l * EDIM * HID;
        tconv_tile(W1 + off, W1h + off, W1l + off, EDIM, HID,
                   (r / 128) * 32, (r % 128) * 32, t);
        return;
    }
    id -= 49152;
    if (id < 49152) {
        int l = id / 4096, r = id % 4096;
        size_t off = (size_t)l * HID * EDIM;
        tconv_tile(W2 + off, W2h + off, W2l + off, HID, EDIM,
                   (r / 32) * 32, (r % 32) * 32, t);
        return;
    }
    id -= 49152;
    tconv_tile(Ue, Ueh, Uel, EDIM, VOC, (id / 1000) * 32, (id % 1000) * 32, t);
}

__global__ void tconv_qkv_kernel(const float* __restrict__ Wq,
                                 const float* __restrict__ Wk,
                                 const float* __restrict__ Wv,
                                 bf16* __restrict__ dhi, bf16* __restrict__ dlo)
{
    __shared__ float t[32][33];
    const int z = blockIdx.z;
    const int l = z / 48;
    const int rr = z % 48;
    const int which = rr / 16;
    const int h = rr % 16;
    const float* src = (which == 0 ? Wq : which == 1 ? Wk : Wv)
                       + ((size_t)(l * NHEAD + h) * EDIM) * HDIM;
    const int i0 = blockIdx.x * 32;
    const int k0 = blockIdx.y * 32;
    const int tx = threadIdx.x, ty = threadIdx.y;
#pragma unroll
    for (int j = 0; j < 4; j++)
        t[ty + 8 * j][tx] = src[(size_t)(k0 + ty + 8 * j) * HDIM + i0 + tx];
    __syncthreads();
    bf16* bh = dhi + (size_t)l * QKVN * EDIM;
    bf16* bl = dlo + (size_t)l * QKVN * EDIM;
#pragma unroll
    for (int j = 0; j < 4; j++) {
        float v = t[tx][ty + 8 * j];
        bf16 hh, ll; split2(v, hh, ll);
        int n = which * 1024 + h * 64 + i0 + ty + 8 * j;
        size_t o = (size_t)n * EDIM + k0 + tx;
        bh[o] = hh; bl[o] = ll;
    }
}

// ---------------- embedding ----------------
__global__ void embed_kernel(const int* __restrict__ tokens,
                             const float* __restrict__ emb,
                             const float* __restrict__ pos,
                             float* __restrict__ X,
                             bf16* __restrict__ Xh, bf16* __restrict__ Xl)
{
    int idx = blockIdx.x * blockDim.x + threadIdx.x;
    int i  = idx / (EDIM / 4);
    int e4 = idx % (EDIM / 4);
    int tok = tokens[i];
    float4 a = ((const float4*)(emb + (size_t)tok * EDIM))[e4];
    float4 p = ((const float4*)(pos + (size_t)(i & 1) * EDIM))[e4];
    float r[4] = { a.x + p.x, a.y + p.y, a.z + p.z, a.w + p.w };
    float4 rf; rf.x = r[0]; rf.y = r[1]; rf.z = r[2]; rf.w = r[3];
    ((float4*)(X + (size_t)i * EDIM))[e4] = rf;
    bf16 hh[4], ll[4];
#pragma unroll
    for (int j = 0; j < 4; j++) split2(r[j], hh[j], ll[j]);
    size_t o = (size_t)i * EDIM + e4 * 4;
#pragma unroll
    for (int j = 0; j < 4; j++) { Xh[o + j] = hh[j]; Xl[o + j] = ll[j]; }
}

// ---------------- attention (T=2), QKV as bf16 hi/lo planes ----------------
__global__ void attn_kernel(const bf16* __restrict__ Qh, const bf16* __restrict__ Ql,
                            bf16* __restrict__ Oh, bf16* __restrict__ Ol)
{
    const int bh = blockIdx.x;
    const int b = bh >> 4;
    const int h = bh & 15;
    const int o = threadIdx.x;
    const size_t q0i = (size_t)(b * 2) * QKVN + h * HDIM + o;
    const size_t q1i = q0i + QKVN;

    float q0 = __bfloat162float(Qh[q0i]) + __bfloat162float(Ql[q0i]);
    float q1 = __bfloat162float(Qh[q1i]) + __bfloat162float(Ql[q1i]);
    float k0 = __bfloat162float(Qh[q0i + 1024]) + __bfloat162float(Ql[q0i + 1024]);
    float k1 = __bfloat162float(Qh[q1i + 1024]) + __bfloat162float(Ql[q1i + 1024]);
    float v0 = __bfloat162float(Qh[q0i + 2048]) + __bfloat162float(Ql[q0i + 2048]);
    float v1 = __bfloat162float(Qh[q1i + 2048]) + __bfloat162float(Ql[q1i + 2048]);

    float d00 = q0 * k0, d01 = q0 * k1, d10 = q1 * k0, d11 = q1 * k1;
    const unsigned mask = 0xffffffffu;
#pragma unroll
    for (int off = 16; off; off >>= 1) {
        d00 += __shfl_down_sync(mask, d00, off);
        d01 += __shfl_down_sync(mask, d01, off);
        d10 += __shfl_down_sync(mask, d10, off);
        d11 += __shfl_down_sync(mask, d11, off);
    }
    __shared__ float part[4][2];
    __shared__ float p[4];
    const int warp = o >> 5;
    if ((o & 31) == 0) {
        part[0][warp] = d00; part[1][warp] = d01;
        part[2][warp] = d10; part[3][warp] = d11;
    }
    __syncthreads();
    if (o == 0) {
        const float scale = 0.125f;
        float s00 = (part[0][0] + part[0][1]) * scale;
        float s01 = (part[1][0] + part[1][1]) * scale;
        float s10 = (part[2][0] + part[2][1]) * scale;
        float s11 = (part[3][0] + part[3][1]) * scale;
        float m0 = fmaxf(s00, s01);
        float e00 = expf(s00 - m0), e01 = expf(s01 - m0);
        float i0 = 1.0f / (e00 + e01);
        float m1 = fmaxf(s10, s11);
        float e10 = expf(s10 - m1), e11 = expf(s11 - m1);
        float i1 = 1.0f / (e10 + e11);
        p[0] = e00 * i0; p[1] = e01 * i0; p[2] = e10 * i1; p[3] = e11 * i1;
    }
    __syncthreads();
    const size_t o0 = (size_t)(b * 2) * EDIM + h * HDIM + o;
    bf16 hh, ll;
    split2(p[0] * v0 + p[1] * v1, hh, ll); Oh[o0] = hh;        Ol[o0] = ll;
    split2(p[2] * v0 + p[3] * v1, hh, ll); Oh[o0 + EDIM] = hh; Ol[o0 + EDIM] = ll;
}

// ---------------- persistent 3xBF16 tensor-core GEMM ----------------
#define MMA_BF16(d, a, b0, b1)                                             \
    asm volatile("mma.sync.aligned.m16n8k16.row.col.f32.bf16.bf16.f32 "    \
                 "{%0,%1,%2,%3},{%4,%5,%6,%7},{%8,%9},{%0,%1,%2,%3};"      \
                 : "+f"(d[0]), "+f"(d[1]), "+f"(d[2]), "+f"(d[3])          \
                 : "r"(a[0]), "r"(a[1]), "r"(a[2]), "r"(a[3]),             \
                   "r"(b0), "r"(b1))

#define LDSM_X4(r, a)                                                       \
    asm volatile("ldmatrix.sync.aligned.m8n8.x4.shared.b16 {%0,%1,%2,%3}, [%4];" \
                 : "=r"((r)[0]), "=r"((r)[1]), "=r"((r)[2]), "=r"((r)[3])   \
                 : "r"(a))

__device__ __forceinline__ void cpa16(uint32_t dst, const void* src) {
    asm volatile("cp.async.cg.shared.global [%0], [%1], 16;\n" :: "r"(dst), "l"(src));
}

#define NSTAGE 4
#define GSTAGE_B 24576
#define GPLANE_B 6144

// Set per-tile global pointers from tile index
#define SET_TILE(T)                                                        \
    do {                                                                   \
        colBase = ((T) % nbx) * 128;                                       \
        rowBase = ((T) / nbx) * 128;                                       \
        gAh = Ah_ + (size_t)(rowBase + lr) * lda + lc;                     \
        gAl = Al_ + (size_t)(rowBase + lr) * lda + lc;                     \
        gBh = Bh_ + (size_t)(colBase + lr) * K + lc;                       \
        gBl = Bl_ + (size_t)(colBase + lr) * K + lc;                       \
    } while (0)

#define LOAD_STAGE(S, KT)                                       \
    do {                                                        \
        uint32_t b_ = sw + (S) * GSTAGE_B;                      \
        int ko_ = (KT) * 16;                                    \
        cpa16(b_,                gAh + ko_);                    \
        cpa16(b_ + GPLANE_B,     gAl + ko_);                    \
        cpa16(b_ + 2 * GPLANE_B, gBh + ko_);                    \
        cpa16(b_ + 3 * GPLANE_B, gBl + ko_);                    \
    } while (0)

template<bool BIAS, bool RELU, bool RES, bool WF32, bool WBF>
__global__ void __launch_bounds__(256, 2)
gemm3p_kernel(const bf16* __restrict__ Ah_, const bf16* __restrict__ Al_, int lda,
              const bf16* __restrict__ Bh_, const bf16* __restrict__ Bl_,
              const float* __restrict__ bias, const float* __restrict__ resid,
              float* __restrict__ Cf, bf16* __restrict__ Ch, bf16* __restrict__ Cl,
              int N, int K, int nbx, int nTiles)
{
    extern __shared__ bf16 smem[];
    const int tid  = threadIdx.x;
    const int lane = tid & 31, warp = tid >> 5;
    const int wm = warp >> 2, wn = warp & 3;
    const int g = lane >> 2, t = lane & 3;

    const int lr = tid >> 1;
    const int lc = (tid & 1) * 8;
    const uint32_t sbase = (uint32_t)__cvta_generic_to_shared(smem);
    const uint32_t sw = sbase + (lr * 24 + lc) * 2;

    const int lq  = lane & 7;
    const int l8  = (lane >> 3) & 1;
    const int l16 = (lane >> 4) & 1;
    uint32_t offA[4], offB[2];
#pragma unroll
    for (int mi = 0; mi < 4; mi++)
        offA[mi] = ((wm * 64 + mi * 16 + lq + 8 * l8) * 24 + 8 * l16) * 2;
#pragma unroll
    for (int pi = 0; pi < 2; pi++)
        offB[pi] = ((wn * 32 + pi * 16 + lq + 8 * l16) * 24 + 8 * l8) * 2;

    int tile = blockIdx.x;
    if (tile >= nTiles) return;

    int rowBase, colBase;
    const bf16 *gAh, *gAl, *gBh, *gBl;
    SET_TILE(tile);

    const int KT = K >> 4;
    LOAD_STAGE(0, 0); asm volatile("cp.async.commit_group;");
    LOAD_STAGE(1, 1); asm volatile("cp.async.commit_group;");
    LOAD_STAGE(2, 2); asm volatile("cp.async.commit_group;");

    float acc[4][4][4];
#pragma unroll
    for (int i = 0; i < 4; i++)
#pragma unroll
        for (int j = 0; j < 4; j++)
#pragma unroll
            for (int q = 0; q < 4; q++) acc[i][j][q] = 0.0f;

    for (;;) {
        for (int kt = 0; kt < KT; ++kt) {
            asm volatile("cp.async.wait_group 2;" ::: "memory");
            __syncthreads();
            if (kt + 3 < KT) LOAD_STAGE((kt + 3) & (NSTAGE - 1), kt + 3);
            asm volatile("cp.async.commit_group;");

            const uint32_t st = sbase + (kt & (NSTAGE - 1)) * GSTAGE_B;
            const uint32_t aH = st;
            const uint32_t aL = st + GPLANE_B;
            const uint32_t bH = st + 2 * GPLANE_B;
            const uint32_t bL = st + 3 * GPLANE_B;

            uint32_t a[4][4];
            uint32_t bh[4][2], bl[4][2];
#pragma unroll
            for (int mi = 0; mi < 4; mi++) LDSM_X4(a[mi], aH + offA[mi]);
#pragma unroll
            for (int pi = 0; pi < 2; pi++) {
                uint32_t r4[4];
                LDSM_X4(r4, bH + offB[pi]);
                bh[2 * pi][0] = r4[0]; bh[2 * pi][1] = r4[1];
                bh[2 * pi + 1][0] = r4[2]; bh[2 * pi + 1][1] = r4[3];
                LDSM_X4(r4, bL + offB[pi]);
                bl[2 * pi][0] = r4[0]; bl[2 * pi][1] = r4[1];
                bl[2 * pi + 1][0] = r4[2]; bl[2 * pi + 1][1] = r4[3];
            }
#pragma unroll
            for (int ni = 0; ni < 4; ni++)
#pragma unroll
                for (int mi = 0; mi < 4; mi++)
                    MMA_BF16(acc[mi][ni], a[mi], bh[ni][0], bh[ni][1]);
#pragma unroll
            for (int ni = 0; ni < 4; ni++)
#pragma unroll
                for (int mi = 0; mi < 4; mi++)
                    MMA_BF16(acc[mi][ni], a[mi], bl[ni][0], bl[ni][1]);
#pragma unroll
            for (int mi = 0; mi < 4; mi++) LDSM_X4(a[mi], aL + offA[mi]);
#pragma unroll
            for (int ni = 0; ni < 4; ni++)
#pragma unroll
                for (int mi = 0; mi < 4; mi++)
                    MMA_BF16(acc[mi][ni], a[mi], bh[ni][0], bh[ni][1]);
        }

        // all reads of smem for this tile are done after this barrier
        __syncthreads();

        const int eRow = rowBase, eCol = colBase;
        const int next = tile + gridDim.x;
        const bool more = next < nTiles;
        if (more) {
            // preload next tile's first 3 stages; overlaps with epilogue below
            SET_TILE(next);
            LOAD_STAGE(0, 0); asm volatile("cp.async.commit_group;");
            LOAD_STAGE(1, 1); asm volatile("cp.async.commit_group;");
            LOAD_STAGE(2, 2); asm volatile("cp.async.commit_group;");
        }

        // ---- epilogue for tile (eRow, eCol) ----
#pragma unroll
        for (int ni = 0; ni < 4; ni++) {
            const int cb = eCol + wn * 32 + ni * 8 + 2 * t;
            float b0 = 0.0f, b1 = 0.0f;
            if (BIAS) { b0 = bias[cb]; b1 = bias[cb + 1]; }
#pragma unroll
            for (int mi = 0; mi < 4; mi++) {
#pragma unroll
                for (int hh = 0; hh < 2; hh++) {
                    const int rr = eRow + wm * 64 + mi * 16 + g + hh * 8;
                    float v0 = acc[mi][ni][hh * 2 + 0];
                    float v1 = acc[mi][ni][hh * 2 + 1];
                    if (BIAS) { v0 += b0; v1 += b1; }
                    if (RELU) { v0 = fmaxf(v0, 0.0f); v1 = fmaxf(v1, 0.0f); }
                    if (RES) {
                        const float2 rv = *(const float2*)&resid[(size_t)rr * N + cb];
                        v0 += rv.x; v1 += rv.y;
                    }
                    if (WF32) {
                        float2 ov; ov.x = v0; ov.y = v1;
                        *(float2*)&Cf[(size_t)rr * N + cb] = ov;
                    }
                    if (WBF) {
                        bf16 h0, l0, h1, l1;
                        split2(v0, h0, l0); split2(v1, h1, l1);
                        __nv_bfloat162 ph; ph.x = h0; ph.y = h1;
                        __nv_bfloat162 pl; pl.x = l0; pl.y = l1;
                        *(__nv_bfloat162*)&Ch[(size_t)rr * N + cb] = ph;
                        *(__nv_bfloat162*)&Cl[(size_t)rr * N + cb] = pl;
                    }
                }
            }
        }

        if (!more) break;
        tile = next;
#pragma unroll
        for (int i = 0; i < 4; i++)
#pragma unroll
            for (int j = 0; j < 4; j++)
#pragma unroll
                for (int q = 0; q < 4; q++) acc[i][j][q] = 0.0f;
    }
}

// ---------------- launcher ----------------
#define NPERS 296   // 148 SMs x 2 CTAs

extern "C" void kernel_launch(void* const* d_in, const int* in_sizes, int n_in,
                              void* d_out, int out_size)
{
    (void)in_sizes; (void)n_in; (void)out_size;
    const int*   tokens  = (const int*)  d_in[0];
    const float* emb     = (const float*)d_in[1];
    const float* pos     = (const float*)d_in[2];
    const float* Wq      = (const float*)d_in[3];
    const float* Wk      = (const float*)d_in[4];
    const float* Wv      = (const float*)d_in[5];
    const float* Wo      = (const float*)d_in[6];
    const float* W1      = (const float*)d_in[7];
    const float* b1      = (const float*)d_in[8];
    const float* W2      = (const float*)d_in[9];
    const float* b2      = (const float*)d_in[10];
    const float* unembed = (const float*)d_in[11];
    float* out = (float*)d_out;

    bf16 *Wqkvh, *Wqkvl, *Woh, *Wol, *W1h, *W1l, *W2h, *W2l, *Ueh, *Uel;
    float *X, *X2;
    bf16 *Xh, *Xl, *X2h, *X2l, *QKVh, *QKVl, *Oh, *Ol, *H1h, *H1l;
    cudaGetSymbolAddress((void**)&Wqkvh, g_Wqkv_h);
    cudaGetSymbolAddress((void**)&Wqkvl, g_Wqkv_l);
    cudaGetSymbolAddress((void**)&Woh,   g_Wo_h);
    cudaGetSymbolAddress((void**)&Wol,   g_Wo_l);
    cudaGetSymbolAddress((void**)&W1h,   g_W1_h);
    cudaGetSymbolAddress((void**)&W1l,   g_W1_l);
    cudaGetSymbolAddress((void**)&W2h,   g_W2_h);
    cudaGetSymbolAddress((void**)&W2l,   g_W2_l);
    cudaGetSymbolAddress((void**)&Ueh,   g_Ue_h);
    cudaGetSymbolAddress((void**)&Uel,   g_Ue_l);
    cudaGetSymbolAddress((void**)&X,    g_X);
    cudaGetSymbolAddress((void**)&X2,   g_X2);
    cudaGetSymbolAddress((void**)&Xh,   g_Xh);
    cudaGetSymbolAddress((void**)&Xl,   g_Xl);
    cudaGetSymbolAddress((void**)&X2h,  g_X2h);
    cudaGetSymbolAddress((void**)&X2l,  g_X2l);
    cudaGetSymbolAddress((void**)&QKVh, g_QKVh);
    cudaGetSymbolAddress((void**)&QKVl, g_QKVl);
    cudaGetSymbolAddress((void**)&Oh,   g_Oh);
    cudaGetSymbolAddress((void**)&Ol,   g_Ol);
    cudaGetSymbolAddress((void**)&H1h,  g_H1h);
    cudaGetSymbolAddress((void**)&H1l,  g_H1l);

    const int SMEM = NSTAGE * GSTAGE_B;   // 96 KB per CTA
    cudaFuncSetAttribute(gemm3p_kernel<false, false, false, false, true >,
                         cudaFuncAttributeMaxDynamicSharedMemorySize, SMEM);
    cudaFuncSetAttribute(gemm3p_kernel<false, false, false, true,  false>,
                         cudaFuncAttributeMaxDynamicSharedMemorySize, SMEM);
    cudaFuncSetAttribute(gemm3p_kernel<false, false, true,  true,  true >,
                         cudaFuncAttributeMaxDynamicSharedMemorySize, SMEM);
    cudaFuncSetAttribute(gemm3p_kernel<true,  true,  false, false, true >,
                         cudaFuncAttributeMaxDynamicSharedMemorySize, SMEM);
    cudaFuncSetAttribute(gemm3p_kernel<true,  true,  true,  true,  true >,
                         cudaFuncAttributeMaxDynamicSharedMemorySize, SMEM);

    // launch order keeps the first QKV GEMM at index 3 for the ncu window
    {
        dim3 b(32, 8);
        tconv_qkv_kernel<<<dim3(2, 32, NLAYER * 48), b>>>(Wq, Wk, Wv, Wqkvh, Wqkvl);   // 0
    }
    embed_kernel<<<(NTOK * EDIM / 4) / 256, 256>>>(tokens, emb, pos, X, Xh, Xl);       // 1
    tconv_fused_kernel<<<142592, dim3(32, 8)>>>(Wo, W1, W2, unembed,                   // 2
        Woh, Wol, W1h, W1l, W2h, W2l, Ueh, Uel);

    const dim3 blk(256);
    for (int l = 0; l < NLAYER; l++) {
        const bf16* wqh = Wqkvh + (size_t)l * QKVN * EDIM;
        const bf16* wql = Wqkvl + (size_t)l * QKVN * EDIM;
        const bf16* woh = Woh + (size_t)l * EDIM * EDIM;
        const bf16* wol = Wol + (size_t)l * EDIM * EDIM;
        const bf16* w1h = W1h + (size_t)l * HID * EDIM;
        const bf16* w1l = W1l + (size_t)l * HID * EDIM;
        const bf16* w2h = W2h + (size_t)l * EDIM * HID;
        const bf16* w2l = W2l + (size_t)l * EDIM * HID;
        const float* b1l = b1 + (size_t)l * HID;
        const float* b2l = b2 + (size_t)l * EDIM;

        // QKV = X @ Wqkv  [4096, 3072]: 768 tiles, persistent 296
        gemm3p_kernel<false, false, false, false, true>
            <<<NPERS, blk, SMEM>>>(
            Xh, Xl, EDIM, wqh, wql, nullptr, nullptr, nullptr, QKVh, QKVl,
            QKVN, EDIM, QKVN / 128, (QKVN / 128) * (NTOK / 128));

        attn_kernel<<<BATCH * NHEAD, 64>>>(QKVh, QKVl, Oh, Ol);

        // X2 = O @ Wo + X  [4096, 1024]: 256 tiles
        gemm3p_kernel<false, false, true, true, true>
            <<<256, blk, SMEM>>>(
            Oh, Ol, EDIM, woh, wol, nullptr, X, X2, X2h, X2l,
            EDIM, EDIM, EDIM / 128, (EDIM / 128) * (NTOK / 128));

        // H1 = relu(X2 @ W1 + b1)  [4096, 4096]: 1024 tiles, persistent 296
        gemm3p_kernel<true, true, false, false, true>
            <<<NPERS, blk, SMEM>>>(
            X2h, X2l, EDIM, w1h, w1l, b1l, nullptr, nullptr, H1h, H1l,
            HID, EDIM, HID / 128, (HID / 128) * (NTOK / 128));

        // X = relu(H1 @ W2 + b2) + X2  [4096, 1024]: 256 tiles
        gemm3p_kernel<true, true, true, true, true>
            <<<256, blk, SMEM>>>(
            H1h, H1l, HID, w2h, w2l, b2l, X2, X, Xh, Xl,
            EDIM, HID, EDIM / 128, (EDIM / 128) * (NTOK / 128));
    }

    // logits = X[:, odd rows, :] @ unembed  [2048, 32000]: 4000 tiles, persistent 296
    gemm3p_kernel<false, false, false, true, false>
        <<<NPERS, blk, SMEM>>>(
        Xh + EDIM, Xl + EDIM, 2 * EDIM, Ueh, Uel, nullptr, nullptr, out, nullptr, nullptr,
        VOC, EDIM, VOC / 128, (VOC / 128) * (BATCH / 128));
}

// round 10
// speedup vs baseline: 1.0589x; 1.0589x over previous
#include <cuda_runtime.h>
#include <cuda_bf16.h>
#include <cstdint>
#include <math.h>

#define NTOK 4096
#define EDIM 1024
#define HID  4096
#define NLAYER 12
#define NHEAD 16
#define HDIM 64
#define BATCH 2048
#define VOC  32000
#define QKVN 3072

typedef __nv_bfloat16 bf16;

// ---------------- scratch (device globals) ----------------
__device__ bf16 g_Wqkv_h[NLAYER * QKVN * EDIM];
__device__ bf16 g_Wqkv_l[NLAYER * QKVN * EDIM];
__device__ bf16 g_Wo_h [NLAYER * EDIM * EDIM];
__device__ bf16 g_Wo_l [NLAYER * EDIM * EDIM];
__device__ bf16 g_W1_h [NLAYER * HID * EDIM];
__device__ bf16 g_W1_l [NLAYER * HID * EDIM];
__device__ bf16 g_W2_h [NLAYER * EDIM * HID];
__device__ bf16 g_W2_l [NLAYER * EDIM * HID];
__device__ bf16 g_Ue_h [VOC * EDIM];
__device__ bf16 g_Ue_l [VOC * EDIM];
__device__ float g_X  [NTOK * EDIM];
__device__ float g_X2 [NTOK * EDIM];
__device__ bf16  g_Xh [NTOK * EDIM];
__device__ bf16  g_Xl [NTOK * EDIM];
__device__ bf16  g_X2h[NTOK * EDIM];
__device__ bf16  g_X2l[NTOK * EDIM];
__device__ float g_QKV[NTOK * QKVN];
__device__ bf16  g_Oh [NTOK * EDIM];
__device__ bf16  g_Ol [NTOK * EDIM];
__device__ bf16  g_H1h[NTOK * HID];
__device__ bf16  g_H1l[NTOK * HID];

__device__ __forceinline__ void split2(float v, bf16& h, bf16& l) {
    h = __float2bfloat16(v);
    l = __float2bfloat16(v - __bfloat162float(h));
}

// ---------------- weight transpose + split ----------------
__global__ void tconv_kernel(const float* __restrict__ src,
                             bf16* __restrict__ dhi, bf16* __restrict__ dlo,
                             int K, int N)
{
    __shared__ float t[32][33];
    const int z = blockIdx.z;
    src += (size_t)z * K * N;
    dhi += (size_t)z * K * N;
    dlo += (size_t)z * K * N;
    const int k0 = blockIdx.y * 32, n0 = blockIdx.x * 32;
    const int tx = threadIdx.x, ty = threadIdx.y;
#pragma unroll
    for (int j = 0; j < 4; j++)
        t[ty + 8 * j][tx] = src[(size_t)(k0 + ty + 8 * j) * N + n0 + tx];
    __syncthreads();
#pragma unroll
    for (int j = 0; j < 4; j++) {
        float v = t[tx][ty + 8 * j];
        bf16 h, l; split2(v, h, l);
        size_t o = (size_t)(n0 + ty + 8 * j) * K + k0 + tx;
        dhi[o] = h; dlo[o] = l;
    }
}

__global__ void tconv_qkv_kernel(const float* __restrict__ Wq,
                                 const float* __restrict__ Wk,
                                 const float* __restrict__ Wv,
                                 bf16* __restrict__ dhi, bf16* __restrict__ dlo)
{
    __shared__ float t[32][33];
    const int z = blockIdx.z;
    const int l = z / 48;
    const int rr = z % 48;
    const int which = rr / 16;
    const int h = rr % 16;
    const float* src = (which == 0 ? Wq : which == 1 ? Wk : Wv)
                       + ((size_t)(l * NHEAD + h) * EDIM) * HDIM;
    const int i0 = blockIdx.x * 32;
    const int k0 = blockIdx.y * 32;
    const int tx = threadIdx.x, ty = threadIdx.y;
#pragma unroll
    for (int j = 0; j < 4; j++)
        t[ty + 8 * j][tx] = src[(size_t)(k0 + ty + 8 * j) * HDIM + i0 + tx];
    __syncthreads();
    bf16* bh = dhi + (size_t)l * QKVN * EDIM;
    bf16* bl = dlo + (size_t)l * QKVN * EDIM;
#pragma unroll
    for (int j = 0; j < 4; j++) {
        float v = t[tx][ty + 8 * j];
        bf16 hh, ll; split2(v, hh, ll);
        int n = which * 1024 + h * 64 + i0 + ty + 8 * j;
        size_t o = (size_t)n * EDIM + k0 + tx;
        bh[o] = hh; bl[o] = ll;
    }
}

// ---------------- embedding ----------------
__global__ void embed_kernel(const int* __restrict__ tokens,
                             const float* __restrict__ emb,
                             const float* __restrict__ pos,
                             float* __restrict__ X,
                             bf16* __restrict__ Xh, bf16* __restrict__ Xl)
{
    int idx = blockIdx.x * blockDim.x + threadIdx.x;
    int i  = idx / (EDIM / 4);
    int e4 = idx % (EDIM / 4);
    int tok = tokens[i];
    float4 a = ((const float4*)(emb + (size_t)tok * EDIM))[e4];
    float4 p = ((const float4*)(pos + (size_t)(i & 1) * EDIM))[e4];
    float r[4] = { a.x + p.x, a.y + p.y, a.z + p.z, a.w + p.w };
    float4 rf; rf.x = r[0]; rf.y = r[1]; rf.z = r[2]; rf.w = r[3];
    ((float4*)(X + (size_t)i * EDIM))[e4] = rf;
    bf16 hh[4], ll[4];
#pragma unroll
    for (int j = 0; j < 4; j++) split2(r[j], hh[j], ll[j]);
    size_t o = (size_t)i * EDIM + e4 * 4;
#pragma unroll
    for (int j = 0; j < 4; j++) { Xh[o + j] = hh[j]; Xl[o + j] = ll[j]; }
}

// ---------------- attention (T=2) ----------------
__global__ void attn_kernel(const float* __restrict__ QKV,
                            bf16* __restrict__ Oh, bf16* __restrict__ Ol)
{
    const int bh = blockIdx.x;
    const int b = bh >> 4;
    const int h = bh & 15;
    const int o = threadIdx.x;
    const size_t q0i = (size_t)(b * 2) * QKVN + h * HDIM + o;
    const size_t q1i = q0i + QKVN;

    float q0 = QKV[q0i],        q1 = QKV[q1i];
    float k0 = QKV[q0i + 1024], k1 = QKV[q1i + 1024];
    float v0 = QKV[q0i + 2048], v1 = QKV[q1i + 2048];

    float d00 = q0 * k0, d01 = q0 * k1, d10 = q1 * k0, d11 = q1 * k1;
    const unsigned mask = 0xffffffffu;
#pragma unroll
    for (int off = 16; off; off >>= 1) {
        d00 += __shfl_down_sync(mask, d00, off);
        d01 += __shfl_down_sync(mask, d01, off);
        d10 += __shfl_down_sync(mask, d10, off);
        d11 += __shfl_down_sync(mask, d11, off);
    }
    __shared__ float part[4][2];
    __shared__ float p[4];
    const int warp = o >> 5;
    if ((o & 31) == 0) {
        part[0][warp] = d00; part[1][warp] = d01;
        part[2][warp] = d10; part[3][warp] = d11;
    }
    __syncthreads();
    if (o == 0) {
        const float scale = 0.125f;
        float s00 = (part[0][0] + part[0][1]) * scale;
        float s01 = (part[1][0] + part[1][1]) * scale;
        float s10 = (part[2][0] + part[2][1]) * scale;
        float s11 = (part[3][0] + part[3][1]) * scale;
        float m0 = fmaxf(s00, s01);
        float e00 = expf(s00 - m0), e01 = expf(s01 - m0);
        float i0 = 1.0f / (e00 + e01);
        float m1 = fmaxf(s10, s11);
        float e10 = expf(s10 - m1), e11 = expf(s11 - m1);
        float i1 = 1.0f / (e10 + e11);
        p[0] = e00 * i0; p[1] = e01 * i0; p[2] = e10 * i1; p[3] = e11 * i1;
    }
    __syncthreads();
    const size_t o0 = (size_t)(b * 2) * EDIM + h * HDIM + o;
    bf16 hh, ll;
    split2(p[0] * v0 + p[1] * v1, hh, ll); Oh[o0] = hh;        Ol[o0] = ll;
    split2(p[2] * v0 + p[3] * v1, hh, ll); Oh[o0 + EDIM] = hh; Ol[o0 + EDIM] = ll;
}

// ---------------- 3xBF16 tensor-core GEMM (de-bunched LDSM schedule) ----------------
#define MMA_BF16(d, a, b0, b1)                                             \
    asm volatile("mma.sync.aligned.m16n8k16.row.col.f32.bf16.bf16.f32 "    \
                 "{%0,%1,%2,%3},{%4,%5,%6,%7},{%8,%9},{%0,%1,%2,%3};"      \
                 : "+f"(d[0]), "+f"(d[1]), "+f"(d[2]), "+f"(d[3])          \
                 : "r"(a[0]), "r"(a[1]), "r"(a[2]), "r"(a[3]),             \
                   "r"(b0), "r"(b1))

#define LDSM_X4(r, a)                                                       \
    asm volatile("ldmatrix.sync.aligned.m8n8.x4.shared.b16 {%0,%1,%2,%3}, [%4];" \
                 : "=r"((r)[0]), "=r"((r)[1]), "=r"((r)[2]), "=r"((r)[3])   \
                 : "r"(a))

__device__ __forceinline__ void cpa16(uint32_t dst, const void* src) {
    asm volatile("cp.async.cg.shared.global [%0], [%1], 16;\n" :: "r"(dst), "l"(src));
}

#define GSTAGE_B 24576
#define GPLANE_B 6144

template<bool BIAS, bool RELU, bool RES, bool WF32, bool WBF>
__global__ void __launch_bounds__(256, 2)
gemm3_kernel(const bf16* __restrict__ Ah_, const bf16* __restrict__ Al_, int lda,
             const bf16* __restrict__ Bh_, const bf16* __restrict__ Bl_,
             const float* __restrict__ bias, const float* __restrict__ resid,
             float* __restrict__ Cf, bf16* __restrict__ Ch, bf16* __restrict__ Cl,
             int N, int K)
{
    extern __shared__ bf16 smem[];
    const int tid  = threadIdx.x;
    const int lane = tid & 31, warp = tid >> 5;
    const int wm = warp >> 2, wn = warp & 3;
    const int g = lane >> 2, t = lane & 3;
    const int rowBase = blockIdx.y * 128;
    const int colBase = blockIdx.x * 128;

    const int lr = tid >> 1;
    const int lc = (tid & 1) * 8;
    const bf16* gAh = Ah_ + (size_t)(rowBase + lr) * lda + lc;
    const bf16* gAl = Al_ + (size_t)(rowBase + lr) * lda + lc;
    const bf16* gBh = Bh_ + (size_t)(colBase + lr) * K + lc;
    const bf16* gBl = Bl_ + (size_t)(colBase + lr) * K + lc;
    const uint32_t sbase = (uint32_t)__cvta_generic_to_shared(smem);
    const uint32_t sw = sbase + (lr * 24 + lc) * 2;

#define LOAD_STAGE(S, KT)                                       \
    do {                                                        \
        uint32_t b_ = sw + (S) * GSTAGE_B;                      \
        int ko_ = (KT) * 16;                                    \
        cpa16(b_,                gAh + ko_);                    \
        cpa16(b_ + GPLANE_B,     gAl + ko_);                    \
        cpa16(b_ + 2 * GPLANE_B, gBh + ko_);                    \
        cpa16(b_ + 3 * GPLANE_B, gBl + ko_);                    \
    } while (0)

    const int lq  = lane & 7;
    const int l8  = (lane >> 3) & 1;
    const int l16 = (lane >> 4) & 1;
    uint32_t offA[4], offB[2];
#pragma unroll
    for (int mi = 0; mi < 4; mi++)
        offA[mi] = ((wm * 64 + mi * 16 + lq + 8 * l8) * 24 + 8 * l16) * 2;
#pragma unroll
    for (int pi = 0; pi < 2; pi++)
        offB[pi] = ((wn * 32 + pi * 16 + lq + 8 * l16) * 24 + 8 * l8) * 2;

    float acc[4][4][4];
#pragma unroll
    for (int i = 0; i < 4; i++)
#pragma unroll
        for (int j = 0; j < 4; j++)
#pragma unroll
            for (int q = 0; q < 4; q++) acc[i][j][q] = 0.0f;

    const int KT = K >> 4;
    LOAD_STAGE(0, 0); asm volatile("cp.async.commit_group;");
    LOAD_STAGE(1, 1); asm volatile("cp.async.commit_group;");

    for (int kt = 0; kt < KT; ++kt) {
        asm volatile("cp.async.wait_group 1;" ::: "memory");
        __syncthreads();
        if (kt + 2 < KT) LOAD_STAGE((kt + 2) % 3, kt + 2);
        asm volatile("cp.async.commit_group;");

        const uint32_t st = sbase + (kt % 3) * GSTAGE_B;
        const uint32_t aH = st;
        const uint32_t aL = st + GPLANE_B;
        const uint32_t bH = st + 2 * GPLANE_B;
        const uint32_t bL = st + 3 * GPLANE_B;

        uint32_t a[4][4];
        uint32_t bh[4][2], bl[4][2];

        // minimal leading fragment loads: A-hi + B-hi only
#pragma unroll
        for (int mi = 0; mi < 4; mi++) LDSM_X4(a[mi], aH + offA[mi]);
        {
            uint32_t r4[4];
            LDSM_X4(r4, bH + offB[0]);
            bh[0][0] = r4[0]; bh[0][1] = r4[1];
            bh[1][0] = r4[2]; bh[1][1] = r4[3];
            LDSM_X4(r4, bH + offB[1]);
            bh[2][0] = r4[0]; bh[2][1] = r4[1];
            bh[3][0] = r4[2]; bh[3][1] = r4[3];
        }

        // term 1: Ah * Bh  (mi outer -> consecutive MMAs reuse A fragment)
#pragma unroll
        for (int mi = 0; mi < 4; mi++)
#pragma unroll
            for (int ni = 0; ni < 4; ni++)
                MMA_BF16(acc[mi][ni], a[mi], bh[ni][0], bh[ni][1]);

        // B-lo loads ride behind term-1's MMA stream
        {
            uint32_t r4[4];
            LDSM_X4(r4, bL + offB[0]);
            bl[0][0] = r4[0]; bl[0][1] = r4[1];
            bl[1][0] = r4[2]; bl[1][1] = r4[3];
            LDSM_X4(r4, bL + offB[1]);
            bl[2][0] = r4[0]; bl[2][1] = r4[1];
            bl[3][0] = r4[2]; bl[3][1] = r4[3];
        }

        // term 2: Ah * Bl
#pragma unroll
        for (int mi = 0; mi < 4; mi++)
#pragma unroll
            for (int ni = 0; ni < 4; ni++)
                MMA_BF16(acc[mi][ni], a[mi], bl[ni][0], bl[ni][1]);

        // A-lo loads ride behind term-2's MMA stream
#pragma unroll
        for (int mi = 0; mi < 4; mi++) LDSM_X4(a[mi], aL + offA[mi]);

        // term 3: Al * Bh
#pragma unroll
        for (int mi = 0; mi < 4; mi++)
#pragma unroll
            for (int ni = 0; ni < 4; ni++)
                MMA_BF16(acc[mi][ni], a[mi], bh[ni][0], bh[ni][1]);
    }
#undef LOAD_STAGE

    // epilogue
#pragma unroll
    for (int ni = 0; ni < 4; ni++) {
        const int cb = colBase + wn * 32 + ni * 8 + 2 * t;
        float b0 = 0.0f, b1 = 0.0f;
        if (BIAS) { b0 = bias[cb]; b1 = bias[cb + 1]; }
#pragma unroll
        for (int mi = 0; mi < 4; mi++) {
#pragma unroll
            for (int hh = 0; hh < 2; hh++) {
                const int rr = rowBase + wm * 64 + mi * 16 + g + hh * 8;
                float v0 = acc[mi][ni][hh * 2 + 0];
                float v1 = acc[mi][ni][hh * 2 + 1];
                if (BIAS) { v0 += b0; v1 += b1; }
                if (RELU) { v0 = fmaxf(v0, 0.0f); v1 = fmaxf(v1, 0.0f); }
                if (RES) {
                    const float2 rv = *(const float2*)&resid[(size_t)rr * N + cb];
                    v0 += rv.x; v1 += rv.y;
                }
                if (WF32) {
                    float2 ov; ov.x = v0; ov.y = v1;
                    *(float2*)&Cf[(size_t)rr * N + cb] = ov;
                }
                if (WBF) {
                    bf16 h0, l0, h1, l1;
                    split2(v0, h0, l0); split2(v1, h1, l1);
                    __nv_bfloat162 ph; ph.x = h0; ph.y = h1;
                    __nv_bfloat162 pl; pl.x = l0; pl.y = l1;
                    *(__nv_bfloat162*)&Ch[(size_t)rr * N + cb] = ph;
                    *(__nv_bfloat162*)&Cl[(size_t)rr * N + cb] = pl;
                }
            }
        }
    }
}

// ---------------- launcher (exact R4 structure) ----------------
extern "C" void kernel_launch(void* const* d_in, const int* in_sizes, int n_in,
                              void* d_out, int out_size)
{
    (void)in_sizes; (void)n_in; (void)out_size;
    const int*   tokens  = (const int*)  d_in[0];
    const float* emb     = (const float*)d_in[1];
    const float* pos     = (const float*)d_in[2];
    const float* Wq      = (const float*)d_in[3];
    const float* Wk      = (const float*)d_in[4];
    const float* Wv      = (const float*)d_in[5];
    const float* Wo      = (const float*)d_in[6];
    const float* W1      = (const float*)d_in[7];
    const float* b1      = (const float*)d_in[8];
    const float* W2      = (const float*)d_in[9];
    const float* b2      = (const float*)d_in[10];
    const float* unembed = (const float*)d_in[11];
    float* out = (float*)d_out;

    bf16 *Wqkvh, *Wqkvl, *Woh, *Wol, *W1h, *W1l, *W2h, *W2l, *Ueh, *Uel;
    float *X, *X2, *QKV;
    bf16 *Xh, *Xl, *X2h, *X2l, *Oh, *Ol, *H1h, *H1l;
    cudaGetSymbolAddress((void**)&Wqkvh, g_Wqkv_h);
    cudaGetSymbolAddress((void**)&Wqkvl, g_Wqkv_l);
    cudaGetSymbolAddress((void**)&Woh,   g_Wo_h);
    cudaGetSymbolAddress((void**)&Wol,   g_Wo_l);
    cudaGetSymbolAddress((void**)&W1h,   g_W1_h);
    cudaGetSymbolAddress((void**)&W1l,   g_W1_l);
    cudaGetSymbolAddress((void**)&W2h,   g_W2_h);
    cudaGetSymbolAddress((void**)&W2l,   g_W2_l);
    cudaGetSymbolAddress((void**)&Ueh,   g_Ue_h);
    cudaGetSymbolAddress((void**)&Uel,   g_Ue_l);
    cudaGetSymbolAddress((void**)&X,   g_X);
    cudaGetSymbolAddress((void**)&X2,  g_X2);
    cudaGetSymbolAddress((void**)&Xh,  g_Xh);
    cudaGetSymbolAddress((void**)&Xl,  g_Xl);
    cudaGetSymbolAddress((void**)&X2h, g_X2h);
    cudaGetSymbolAddress((void**)&X2l, g_X2l);
    cudaGetSymbolAddress((void**)&QKV, g_QKV);
    cudaGetSymbolAddress((void**)&Oh,  g_Oh);
    cudaGetSymbolAddress((void**)&Ol,  g_Ol);
    cudaGetSymbolAddress((void**)&H1h, g_H1h);
    cudaGetSymbolAddress((void**)&H1l, g_H1l);

    const int SMEM = 3 * GSTAGE_B;
    cudaFuncSetAttribute(gemm3_kernel<false, false, false, true,  false>,
                         cudaFuncAttributeMaxDynamicSharedMemorySize, SMEM);
    cudaFuncSetAttribute(gemm3_kernel<false, false, true,  true,  true >,
                         cudaFuncAttributeMaxDynamicSharedMemorySize, SMEM);
    cudaFuncSetAttribute(gemm3_kernel<true,  true,  false, false, true >,
                         cudaFuncAttributeMaxDynamicSharedMemorySize, SMEM);
    cudaFuncSetAttribute(gemm3_kernel<true,  true,  true,  true,  true >,
                         cudaFuncAttributeMaxDynamicSharedMemorySize, SMEM);

    // ---- weight prep (transpose + bf16 split) ----
    {
        dim3 b(32, 8);
        tconv_qkv_kernel<<<dim3(2, 32, NLAYER * 48), b>>>(Wq, Wk, Wv, Wqkvh, Wqkvl);
        tconv_kernel<<<dim3(32, 32, NLAYER), b>>>(Wo, Woh, Wol, EDIM, EDIM);
        tconv_kernel<<<dim3(128, 32, NLAYER), b>>>(W1, W1h, W1l, EDIM, HID);
        tconv_kernel<<<dim3(32, 128, NLAYER), b>>>(W2, W2h, W2l, HID, EDIM);
        tconv_kernel<<<dim3(1000, 32, 1), b>>>(unembed, Ueh, Uel, EDIM, VOC);
    }

    embed_kernel<<<(NTOK * EDIM / 4) / 256, 256>>>(tokens, emb, pos, X, Xh, Xl);

    const dim3 blk(256);
    for (int l = 0; l < NLAYER; l++) {
        const bf16* wqh = Wqkvh + (size_t)l * QKVN * EDIM;
        const bf16* wql = Wqkvl + (size_t)l * QKVN * EDIM;
        const bf16* woh = Woh + (size_t)l * EDIM * EDIM;
        const bf16* wol = Wol + (size_t)l * EDIM * EDIM;
        const bf16* w1h = W1h + (size_t)l * HID * EDIM;
        const bf16* w1l = W1l + (size_t)l * HID * EDIM;
        const bf16* w2h = W2h + (size_t)l * EDIM * HID;
        const bf16* w2l = W2l + (size_t)l * EDIM * HID;
        const float* b1l = b1 + (size_t)l * HID;
        const float* b2l = b2 + (size_t)l * EDIM;

        // QKV = X @ Wqkv            [4096, 3072]
        gemm3_kernel<false, false, false, true, false>
            <<<dim3(QKVN / 128, NTOK / 128), blk, SMEM>>>(
            Xh, Xl, EDIM, wqh, wql, nullptr, nullptr, QKV, nullptr, nullptr, QKVN, EDIM);

        attn_kernel<<<BATCH * NHEAD, 64>>>(QKV, Oh, Ol);

        // X2 = O @ Wo + X           [4096, 1024]  (+ split planes)
        gemm3_kernel<false, false, true, true, true>
            <<<dim3(EDIM / 128, NTOK / 128), blk, SMEM>>>(
            Oh, Ol, EDIM, woh, wol, nullptr, X, X2, X2h, X2l, EDIM, EDIM);

        // H1 = relu(X2 @ W1 + b1)   [4096, 4096]  (split planes only)
        gemm3_kernel<true, true, false, false, true>
            <<<dim3(HID / 128, NTOK / 128), blk, SMEM>>>(
            X2h, X2l, EDIM, w1h, w1l, b1l, nullptr, nullptr, H1h, H1l, HID, EDIM);

        // X = relu(H1 @ W2 + b2) + X2   [4096, 1024]  (+ split planes)
        gemm3_kernel<true, true, true, true, true>
            <<<dim3(EDIM / 128, NTOK / 128), blk, SMEM>>>(
            H1h, H1l, HID, w2h, w2l, b2l, X2, X, Xh, Xl, EDIM, HID);
    }

    // logits = X[:, odd rows, :] @ unembed    [2048, 32000]
    gemm3_kernel<false, false, false, true, false>
        <<<dim3(VOC / 128, BATCH / 128), blk, SMEM>>>(
        Xh + EDIM, Xl + EDIM, 2 * EDIM, Ueh, Uel, nullptr, nullptr, out, nullptr, nullptr,
        VOC, EDIM);
}

// round 11
// speedup vs baseline: 1.0688x; 1.0093x over previous
#include <cuda_runtime.h>
#include <cuda_bf16.h>
#include <cstdint>
#include <math.h>

#define NTOK 4096
#define EDIM 1024
#define HID  4096
#define NLAYER 12
#define NHEAD 16
#define HDIM 64
#define BATCH 2048
#define VOC  32000
#define QKVN 3072

typedef __nv_bfloat16 bf16;

// ---------------- scratch (device globals) ----------------
__device__ bf16 g_Wqkv_h[NLAYER * QKVN * EDIM];
__device__ bf16 g_Wqkv_l[NLAYER * QKVN * EDIM];
__device__ bf16 g_Wo_h [NLAYER * EDIM * EDIM];
__device__ bf16 g_Wo_l [NLAYER * EDIM * EDIM];
__device__ bf16 g_W1_h [NLAYER * HID * EDIM];
__device__ bf16 g_W1_l [NLAYER * HID * EDIM];
__device__ bf16 g_W2_h [NLAYER * EDIM * HID];
__device__ bf16 g_W2_l [NLAYER * EDIM * HID];
__device__ bf16 g_Ue_h [VOC * EDIM];
__device__ bf16 g_Ue_l [VOC * EDIM];
__device__ float g_X  [NTOK * EDIM];
__device__ float g_X2 [NTOK * EDIM];
__device__ bf16  g_Xh [NTOK * EDIM];
__device__ bf16  g_Xl [NTOK * EDIM];
__device__ bf16  g_X2h[NTOK * EDIM];
__device__ bf16  g_X2l[NTOK * EDIM];
__device__ float g_QKV[NTOK * QKVN];
__device__ bf16  g_Oh [NTOK * EDIM];
__device__ bf16  g_Ol [NTOK * EDIM];
__device__ bf16  g_H1h[NTOK * HID];
__device__ bf16  g_H1l[NTOK * HID];

__device__ __forceinline__ void split2(float v, bf16& h, bf16& l) {
    h = __float2bfloat16(v);
    l = __float2bfloat16(v - __bfloat162float(h));
}

// ---------------- weight transpose + split (paired-k vector stores) ----------------
__global__ void tconv_kernel(const float* __restrict__ src,
                             bf16* __restrict__ dhi, bf16* __restrict__ dlo,
                             int K, int N)
{
    __shared__ float t[32][33];
    const int z = blockIdx.z;
    src += (size_t)z * K * N;
    dhi += (size_t)z * K * N;
    dlo += (size_t)z * K * N;
    const int k0 = blockIdx.y * 32, n0 = blockIdx.x * 32;
    const int tx = threadIdx.x, ty = threadIdx.y;
#pragma unroll
    for (int j = 0; j < 4; j++)
        t[ty + 8 * j][tx] = src[(size_t)(k0 + ty + 8 * j) * N + n0 + tx];
    __syncthreads();
    const int s  = ty * 32 + tx;
    const int kp = s & 15;          // k-pair index
    const int nb = s >> 4;          // n base (0..15)
#pragma unroll
    for (int j = 0; j < 2; j++) {
        const int n = nb + 16 * j;
        float v0 = t[2 * kp][n];
        float v1 = t[2 * kp + 1][n];
        bf16 h0, l0, h1, l1;
        split2(v0, h0, l0); split2(v1, h1, l1);
        __nv_bfloat162 ph; ph.x = h0; ph.y = h1;
        __nv_bfloat162 pl; pl.x = l0; pl.y = l1;
        size_t o = (size_t)(n0 + n) * K + k0 + 2 * kp;
        *(__nv_bfloat162*)&dhi[o] = ph;
        *(__nv_bfloat162*)&dlo[o] = pl;
    }
}

__global__ void tconv_qkv_kernel(const float* __restrict__ Wq,
                                 const float* __restrict__ Wk,
                                 const float* __restrict__ Wv,
                                 bf16* __restrict__ dhi, bf16* __restrict__ dlo)
{
    __shared__ float t[32][33];
    const int z = blockIdx.z;
    const int l = z / 48;
    const int rr = z % 48;
    const int which = rr / 16;
    const int h = rr % 16;
    const float* src = (which == 0 ? Wq : which == 1 ? Wk : Wv)
                       + ((size_t)(l * NHEAD + h) * EDIM) * HDIM;
    const int i0 = blockIdx.x * 32;
    const int k0 = blockIdx.y * 32;
    const int tx = threadIdx.x, ty = threadIdx.y;
#pragma unroll
    for (int j = 0; j < 4; j++)
        t[ty + 8 * j][tx] = src[(size_t)(k0 + ty + 8 * j) * HDIM + i0 + tx];
    __syncthreads();
    bf16* bh = dhi + (size_t)l * QKVN * EDIM;
    bf16* bl = dlo + (size_t)l * QKVN * EDIM;
    const int s  = ty * 32 + tx;
    const int kp = s & 15;
    const int nb = s >> 4;
#pragma unroll
    for (int j = 0; j < 2; j++) {
        const int ni = nb + 16 * j;
        float v0 = t[2 * kp][ni];
        float v1 = t[2 * kp + 1][ni];
        bf16 h0, l0, h1, l1;
        split2(v0, h0, l0); split2(v1, h1, l1);
        __nv_bfloat162 ph; ph.x = h0; ph.y = h1;
        __nv_bfloat162 pl; pl.x = l0; pl.y = l1;
        int n = which * 1024 + h * 64 + i0 + ni;
        size_t o = (size_t)n * EDIM + k0 + 2 * kp;
        *(__nv_bfloat162*)&bh[o] = ph;
        *(__nv_bfloat162*)&bl[o] = pl;
    }
}

// ---------------- embedding ----------------
__global__ void embed_kernel(const int* __restrict__ tokens,
                             const float* __restrict__ emb,
                             const float* __restrict__ pos,
                             float* __restrict__ X,
                             bf16* __restrict__ Xh, bf16* __restrict__ Xl)
{
    int idx = blockIdx.x * blockDim.x + threadIdx.x;
    int i  = idx / (EDIM / 4);
    int e4 = idx % (EDIM / 4);
    int tok = tokens[i];
    float4 a = ((const float4*)(emb + (size_t)tok * EDIM))[e4];
    float4 p = ((const float4*)(pos + (size_t)(i & 1) * EDIM))[e4];
    float r[4] = { a.x + p.x, a.y + p.y, a.z + p.z, a.w + p.w };
    float4 rf; rf.x = r[0]; rf.y = r[1]; rf.z = r[2]; rf.w = r[3];
    ((float4*)(X + (size_t)i * EDIM))[e4] = rf;
    bf16 hh[4], ll[4];
#pragma unroll
    for (int j = 0; j < 4; j++) split2(r[j], hh[j], ll[j]);
    size_t o = (size_t)i * EDIM + e4 * 4;
#pragma unroll
    for (int j = 0; j < 4; j++) { Xh[o + j] = hh[j]; Xl[o + j] = ll[j]; }
}

// ---------------- attention (T=2): one warp per (b,h), no smem ----------------
__global__ void attn_kernel(const float* __restrict__ QKV,
                            bf16* __restrict__ Oh, bf16* __restrict__ Ol)
{
    const int w = blockIdx.x * 8 + (threadIdx.x >> 5);   // bh index
    const int lane = threadIdx.x & 31;
    const int b = w >> 4;
    const int h = w & 15;
    const size_t base = (size_t)(b * 2) * QKVN + h * HDIM + lane;

    float q0a = QKV[base],             q0b = QKV[base + 32];
    float q1a = QKV[base + QKVN],      q1b = QKV[base + QKVN + 32];
    float k0a = QKV[base + 1024],      k0b = QKV[base + 1056];
    float k1a = QKV[base + QKVN + 1024], k1b = QKV[base + QKVN + 1056];
    float v0a = QKV[base + 2048],      v0b = QKV[base + 2080];
    float v1a = QKV[base + QKVN + 2048], v1b = QKV[base + QKVN + 2080];

    float d00 = q0a * k0a + q0b * k0b;
    float d01 = q0a * k1a + q0b * k1b;
    float d10 = q1a * k0a + q1b * k0b;
    float d11 = q1a * k1a + q1b * k1b;
#pragma unroll
    for (int off = 16; off; off >>= 1) {
        d00 += __shfl_xor_sync(0xffffffffu, d00, off);
        d01 += __shfl_xor_sync(0xffffffffu, d01, off);
        d10 += __shfl_xor_sync(0xffffffffu, d10, off);
        d11 += __shfl_xor_sync(0xffffffffu, d11, off);
    }
    const float scale = 0.125f;
    float s00 = d00 * scale, s01 = d01 * scale;
    float s10 = d10 * scale, s11 = d11 * scale;
    float m0 = fmaxf(s00, s01), m1 = fmaxf(s10, s11);
    float e00 = expf(s00 - m0), e01 = expf(s01 - m0);
    float i0 = 1.0f / (e00 + e01);
    float e10 = expf(s10 - m1), e11 = expf(s11 - m1);
    float i1 = 1.0f / (e10 + e11);
    float p0 = e00 * i0, p1 = e01 * i0, p2 = e10 * i1, p3 = e11 * i1;

    const size_t o0 = (size_t)(b * 2) * EDIM + h * HDIM + lane;
    bf16 hh, ll;
    split2(p0 * v0a + p1 * v1a, hh, ll); Oh[o0] = hh;             Ol[o0] = ll;
    split2(p0 * v0b + p1 * v1b, hh, ll); Oh[o0 + 32] = hh;        Ol[o0 + 32] = ll;
    split2(p2 * v0a + p3 * v1a, hh, ll); Oh[o0 + EDIM] = hh;      Ol[o0 + EDIM] = ll;
    split2(p2 * v0b + p3 * v1b, hh, ll); Oh[o0 + EDIM + 32] = hh; Ol[o0 + EDIM + 32] = ll;
}

// ---------------- 3xBF16 tensor-core GEMM (champion config) ----------------
#define MMA_BF16(d, a, b0, b1)                                             \
    asm volatile("mma.sync.aligned.m16n8k16.row.col.f32.bf16.bf16.f32 "    \
                 "{%0,%1,%2,%3},{%4,%5,%6,%7},{%8,%9},{%0,%1,%2,%3};"      \
                 : "+f"(d[0]), "+f"(d[1]), "+f"(d[2]), "+f"(d[3])          \
                 : "r"(a[0]), "r"(a[1]), "r"(a[2]), "r"(a[3]),             \
                   "r"(b0), "r"(b1))

#define LDSM_X4(r, a)                                                       \
    asm volatile("ldmatrix.sync.aligned.m8n8.x4.shared.b16 {%0,%1,%2,%3}, [%4];" \
                 : "=r"((r)[0]), "=r"((r)[1]), "=r"((r)[2]), "=r"((r)[3])   \
                 : "r"(a))

__device__ __forceinline__ void cpa16(uint32_t dst, const void* src) {
    asm volatile("cp.async.cg.shared.global [%0], [%1], 16;\n" :: "r"(dst), "l"(src));
}

#define GSTAGE_B 24576
#define GPLANE_B 6144

template<bool BIAS, bool RELU, bool RES, bool WF32, bool WBF>
__global__ void __launch_bounds__(256, 2)
gemm3_kernel(const bf16* __restrict__ Ah_, const bf16* __restrict__ Al_, int lda,
             const bf16* __restrict__ Bh_, const bf16* __restrict__ Bl_,
             const float* __restrict__ bias, const float* __restrict__ resid,
             float* __restrict__ Cf, bf16* __restrict__ Ch, bf16* __restrict__ Cl,
             int N, int K)
{
    extern __shared__ bf16 smem[];
    const int tid  = threadIdx.x;
    const int lane = tid & 31, warp = tid >> 5;
    const int wm = warp >> 2, wn = warp & 3;
    const int g = lane >> 2, t = lane & 3;
    const int rowBase = blockIdx.y * 128;
    const int colBase = blockIdx.x * 128;

    const int lr = tid >> 1;
    const int lc = (tid & 1) * 8;
    const bf16* gAh = Ah_ + (size_t)(rowBase + lr) * lda + lc;
    const bf16* gAl = Al_ + (size_t)(rowBase + lr) * lda + lc;
    const bf16* gBh = Bh_ + (size_t)(colBase + lr) * K + lc;
    const bf16* gBl = Bl_ + (size_t)(colBase + lr) * K + lc;
    const uint32_t sbase = (uint32_t)__cvta_generic_to_shared(smem);
    const uint32_t sw = sbase + (lr * 24 + lc) * 2;

#define LOAD_STAGE(S, KT)                                       \
    do {                                                        \
        uint32_t b_ = sw + (S) * GSTAGE_B;                      \
        int ko_ = (KT) * 16;                                    \
        cpa16(b_,                gAh + ko_);                    \
        cpa16(b_ + GPLANE_B,     gAl + ko_);                    \
        cpa16(b_ + 2 * GPLANE_B, gBh + ko_);                    \
        cpa16(b_ + 3 * GPLANE_B, gBl + ko_);                    \
    } while (0)

    const int lq  = lane & 7;
    const int l8  = (lane >> 3) & 1;
    const int l16 = (lane >> 4) & 1;
    uint32_t offA[4], offB[2];
#pragma unroll
    for (int mi = 0; mi < 4; mi++)
        offA[mi] = ((wm * 64 + mi * 16 + lq + 8 * l8) * 24 + 8 * l16) * 2;
#pragma unroll
    for (int pi = 0; pi < 2; pi++)
        offB[pi] = ((wn * 32 + pi * 16 + lq + 8 * l16) * 24 + 8 * l8) * 2;

    float acc[4][4][4];
#pragma unroll
    for (int i = 0; i < 4; i++)
#pragma unroll
        for (int j = 0; j < 4; j++)
#pragma unroll
            for (int q = 0; q < 4; q++) acc[i][j][q] = 0.0f;

    const int KT = K >> 4;
    LOAD_STAGE(0, 0); asm volatile("cp.async.commit_group;");
    LOAD_STAGE(1, 1); asm volatile("cp.async.commit_group;");

    for (int kt = 0; kt < KT; ++kt) {
        asm volatile("cp.async.wait_group 1;" ::: "memory");
        __syncthreads();
        if (kt + 2 < KT) LOAD_STAGE((kt + 2) % 3, kt + 2);
        asm volatile("cp.async.commit_group;");

        const uint32_t st = sbase + (kt % 3) * GSTAGE_B;
        const uint32_t aH = st;
        const uint32_t aL = st + GPLANE_B;
        const uint32_t bH = st + 2 * GPLANE_B;
        const uint32_t bL = st + 3 * GPLANE_B;

        uint32_t a[4][4];
        uint32_t bh[4][2], bl[4][2];
#pragma unroll
        for (int mi = 0; mi < 4; mi++) LDSM_X4(a[mi], aH + offA[mi]);
        {
            uint32_t r4[4];
            LDSM_X4(r4, bH + offB[0]);
            bh[0][0] = r4[0]; bh[0][1] = r4[1];
            bh[1][0] = r4[2]; bh[1][1] = r4[3];
            LDSM_X4(r4, bH + offB[1]);
            bh[2][0] = r4[0]; bh[2][1] = r4[1];
            bh[3][0] = r4[2]; bh[3][1] = r4[3];
        }

#pragma unroll
        for (int mi = 0; mi < 4; mi++)
#pragma unroll
            for (int ni = 0; ni < 4; ni++)
                MMA_BF16(acc[mi][ni], a[mi], bh[ni][0], bh[ni][1]);

        {
            uint32_t r4[4];
            LDSM_X4(r4, bL + offB[0]);
            bl[0][0] = r4[0]; bl[0][1] = r4[1];
            bl[1][0] = r4[2]; bl[1][1] = r4[3];
            LDSM_X4(r4, bL + offB[1]);
            bl[2][0] = r4[0]; bl[2][1] = r4[1];
            bl[3][0] = r4[2]; bl[3][1] = r4[3];
        }

#pragma unroll
        for (int mi = 0; mi < 4; mi++)
#pragma unroll
            for (int ni = 0; ni < 4; ni++)
                MMA_BF16(acc[mi][ni], a[mi], bl[ni][0], bl[ni][1]);

#pragma unroll
        for (int mi = 0; mi < 4; mi++) LDSM_X4(a[mi], aL + offA[mi]);

#pragma unroll
        for (int mi = 0; mi < 4; mi++)
#pragma unroll
            for (int ni = 0; ni < 4; ni++)
                MMA_BF16(acc[mi][ni], a[mi], bh[ni][0], bh[ni][1]);
    }
#undef LOAD_STAGE

    // epilogue
#pragma unroll
    for (int ni = 0; ni < 4; ni++) {
        const int cb = colBase + wn * 32 + ni * 8 + 2 * t;
        float b0 = 0.0f, b1 = 0.0f;
        if (BIAS) { b0 = bias[cb]; b1 = bias[cb + 1]; }
#pragma unroll
        for (int mi = 0; mi < 4; mi++) {
#pragma unroll
            for (int hh = 0; hh < 2; hh++) {
                const int rr = rowBase + wm * 64 + mi * 16 + g + hh * 8;
                float v0 = acc[mi][ni][hh * 2 + 0];
                float v1 = acc[mi][ni][hh * 2 + 1];
                if (BIAS) { v0 += b0; v1 += b1; }
                if (RELU) { v0 = fmaxf(v0, 0.0f); v1 = fmaxf(v1, 0.0f); }
                if (RES) {
                    const float2 rv = *(const float2*)&resid[(size_t)rr * N + cb];
                    v0 += rv.x; v1 += rv.y;
                }
                if (WF32) {
                    float2 ov; ov.x = v0; ov.y = v1;
                    *(float2*)&Cf[(size_t)rr * N + cb] = ov;
                }
                if (WBF) {
                    bf16 h0, l0, h1, l1;
                    split2(v0, h0, l0); split2(v1, h1, l1);
                    __nv_bfloat162 ph; ph.x = h0; ph.y = h1;
                    __nv_bfloat162 pl; pl.x = l0; pl.y = l1;
                    *(__nv_bfloat162*)&Ch[(size_t)rr * N + cb] = ph;
                    *(__nv_bfloat162*)&Cl[(size_t)rr * N + cb] = pl;
                }
            }
        }
    }
}

// ---------------- launcher ----------------
extern "C" void kernel_launch(void* const* d_in, const int* in_sizes, int n_in,
                              void* d_out, int out_size)
{
    (void)in_sizes; (void)n_in; (void)out_size;
    const int*   tokens  = (const int*)  d_in[0];
    const float* emb     = (const float*)d_in[1];
    const float* pos     = (const float*)d_in[2];
    const float* Wq      = (const float*)d_in[3];
    const float* Wk      = (const float*)d_in[4];
    const float* Wv      = (const float*)d_in[5];
    const float* Wo      = (const float*)d_in[6];
    const float* W1      = (const float*)d_in[7];
    const float* b1      = (const float*)d_in[8];
    const float* W2      = (const float*)d_in[9];
    const float* b2      = (const float*)d_in[10];
    const float* unembed = (const float*)d_in[11];
    float* out = (float*)d_out;

    bf16 *Wqkvh, *Wqkvl, *Woh, *Wol, *W1h, *W1l, *W2h, *W2l, *Ueh, *Uel;
    float *X, *X2, *QKV;
    bf16 *Xh, *Xl, *X2h, *X2l, *Oh, *Ol, *H1h, *H1l;
    cudaGetSymbolAddress((void**)&Wqkvh, g_Wqkv_h);
    cudaGetSymbolAddress((void**)&Wqkvl, g_Wqkv_l);
    cudaGetSymbolAddress((void**)&Woh,   g_Wo_h);
    cudaGetSymbolAddress((void**)&Wol,   g_Wo_l);
    cudaGetSymbolAddress((void**)&W1h,   g_W1_h);
    cudaGetSymbolAddress((void**)&W1l,   g_W1_l);
    cudaGetSymbolAddress((void**)&W2h,   g_W2_h);
    cudaGetSymbolAddress((void**)&W2l,   g_W2_l);
    cudaGetSymbolAddress((void**)&Ueh,   g_Ue_h);
    cudaGetSymbolAddress((void**)&Uel,   g_Ue_l);
    cudaGetSymbolAddress((void**)&X,   g_X);
    cudaGetSymbolAddress((void**)&X2,  g_X2);
    cudaGetSymbolAddress((void**)&Xh,  g_Xh);
    cudaGetSymbolAddress((void**)&Xl,  g_Xl);
    cudaGetSymbolAddress((void**)&X2h, g_X2h);
    cudaGetSymbolAddress((void**)&X2l, g_X2l);
    cudaGetSymbolAddress((void**)&QKV, g_QKV);
    cudaGetSymbolAddress((void**)&Oh,  g_Oh);
    cudaGetSymbolAddress((void**)&Ol,  g_Ol);
    cudaGetSymbolAddress((void**)&H1h, g_H1h);
    cudaGetSymbolAddress((void**)&H1l, g_H1l);

    const int SMEM = 3 * GSTAGE_B;
    cudaFuncSetAttribute(gemm3_kernel<false, false, false, true,  false>,
                         cudaFuncAttributeMaxDynamicSharedMemorySize, SMEM);
    cudaFuncSetAttribute(gemm3_kernel<false, false, true,  true,  true >,
                         cudaFuncAttributeMaxDynamicSharedMemorySize, SMEM);
    cudaFuncSetAttribute(gemm3_kernel<true,  true,  false, false, true >,
                         cudaFuncAttributeMaxDynamicSharedMemorySize, SMEM);
    cudaFuncSetAttribute(gemm3_kernel<true,  true,  true,  true,  true >,
                         cudaFuncAttributeMaxDynamicSharedMemorySize, SMEM);

    // ---- weight prep (transpose + bf16 split) ----
    {
        dim3 b(32, 8);
        tconv_qkv_kernel<<<dim3(2, 32, NLAYER * 48), b>>>(Wq, Wk, Wv, Wqkvh, Wqkvl);
        tconv_kernel<<<dim3(32, 32, NLAYER), b>>>(Wo, Woh, Wol, EDIM, EDIM);
        tconv_kernel<<<dim3(128, 32, NLAYER), b>>>(W1, W1h, W1l, EDIM, HID);
        tconv_kernel<<<dim3(32, 128, NLAYER), b>>>(W2, W2h, W2l, HID, EDIM);
        tconv_kernel<<<dim3(1000, 32, 1), b>>>(unembed, Ueh, Uel, EDIM, VOC);
    }

    embed_kernel<<<(NTOK * EDIM / 4) / 256, 256>>>(tokens, emb, pos, X, Xh, Xl);

    const dim3 blk(256);
    for (int l = 0; l < NLAYER; l++) {
        const bf16* wqh = Wqkvh + (size_t)l * QKVN * EDIM;
        const bf16* wql = Wqkvl + (size_t)l * QKVN * EDIM;
        const bf16* woh = Woh + (size_t)l * EDIM * EDIM;
        const bf16* wol = Wol + (size_t)l * EDIM * EDIM;
        const bf16* w1h = W1h + (size_t)l * HID * EDIM;
        const bf16* w1l = W1l + (size_t)l * HID * EDIM;
        const bf16* w2h = W2h + (size_t)l * EDIM * HID;
        const bf16* w2l = W2l + (size_t)l * EDIM * HID;
        const float* b1l = b1 + (size_t)l * HID;
        const float* b2l = b2 + (size_t)l * EDIM;

        // QKV = X @ Wqkv            [4096, 3072]
        gemm3_kernel<false, false, false, true, false>
            <<<dim3(QKVN / 128, NTOK / 128), blk, SMEM>>>(
            Xh, Xl, EDIM, wqh, wql, nullptr, nullptr, QKV, nullptr, nullptr, QKVN, EDIM);

        attn_kernel<<<BATCH * NHEAD / 8, 256>>>(QKV, Oh, Ol);

        // X2 = O @ Wo + X           [4096, 1024]  (+ split planes)
        gemm3_kernel<false, false, true, true, true>
            <<<dim3(EDIM / 128, NTOK / 128), blk, SMEM>>>(
            Oh, Ol, EDIM, woh, wol, nullptr, X, X2, X2h, X2l, EDIM, EDIM);

        // H1 = relu(X2 @ W1 + b1)   [4096, 4096]  (split planes only)
        gemm3_kernel<true, true, false, false, true>
            <<<dim3(HID / 128, NTOK / 128), blk, SMEM>>>(
            X2h, X2l, EDIM, w1h, w1l, b1l, nullptr, nullptr, H1h, H1l, HID, EDIM);

        // X = relu(H1 @ W2 + b2) + X2   [4096, 1024]  (+ split planes)
        gemm3_kernel<true, true, true, true, true>
            <<<dim3(EDIM / 128, NTOK / 128), blk, SMEM>>>(
            H1h, H1l, HID, w2h, w2l, b2l, X2, X, Xh, Xl, EDIM, HID);
    }

    // logits = X[:, odd rows, :] @ unembed    [2048, 32000]
    gemm3_kernel<false, false, false, true, false>
        <<<dim3(VOC / 128, BATCH / 128), blk, SMEM>>>(
        Xh + EDIM, Xl + EDIM, 2 * EDIM, Ueh, Uel, nullptr, nullptr, out, nullptr, nullptr,
        VOC, EDIM);
}

// round 13
// speedup vs baseline: 1.0712x; 1.0022x over previous
#include <cuda_runtime.h>
#include <cuda_bf16.h>
#include <cstdint>
#include <math.h>

#define NTOK 4096
#define EDIM 1024
#define HID  4096
#define NLAYER 12
#define NHEAD 16
#define HDIM 64
#define BATCH 2048
#define VOC  32000
#define QKVN 3072

typedef __nv_bfloat16 bf16;

struct alignas(8) bf4 { __nv_bfloat162 a, b; };

// ---------------- scratch (device globals) ----------------
__device__ bf16 g_Wqkv_h[NLAYER * QKVN * EDIM];
__device__ bf16 g_Wqkv_l[NLAYER * QKVN * EDIM];
__device__ bf16 g_Wo_h [NLAYER * EDIM * EDIM];
__device__ bf16 g_Wo_l [NLAYER * EDIM * EDIM];
__device__ bf16 g_W1_h [NLAYER * HID * EDIM];
__device__ bf16 g_W1_l [NLAYER * HID * EDIM];
__device__ bf16 g_W2_h [NLAYER * EDIM * HID];
__device__ bf16 g_W2_l [NLAYER * EDIM * HID];
__device__ bf16 g_Ue_h [VOC * EDIM];
__device__ bf16 g_Ue_l [VOC * EDIM];
__device__ float g_QKV[NTOK * QKVN];
__device__ bf16  g_Xh [NTOK * EDIM];
__device__ bf16  g_Xl [NTOK * EDIM];
__device__ bf16  g_X2h[NTOK * EDIM];
__device__ bf16  g_X2l[NTOK * EDIM];
__device__ bf16  g_Oh [NTOK * EDIM];
__device__ bf16  g_Ol [NTOK * EDIM];
__device__ bf16  g_H1h[NTOK * HID];
__device__ bf16  g_H1l[NTOK * HID];

__device__ __forceinline__ void split2(float v, bf16& h, bf16& l) {
    h = __float2bfloat16(v);
    l = __float2bfloat16(v - __bfloat162float(h));
}

// ---------------- weight transpose + split: 64(K)x32(N) tiles, 8B stores ----------------
// 256 threads: kq = s&15 (16 k-quads of 4), nb = s>>4 (16 n), 2 n-iterations.
__global__ void tconv_kernel(const float* __restrict__ src,
                             bf16* __restrict__ dhi, bf16* __restrict__ dlo,
                             int K, int N)
{
    __shared__ float t[64][33];
    const int z = blockIdx.z;
    src += (size_t)z * K * N;
    dhi += (size_t)z * K * N;
    dlo += (size_t)z * K * N;
    const int k0 = blockIdx.y * 64, n0 = blockIdx.x * 32;
    const int tx = threadIdx.x, ty = threadIdx.y;
#pragma unroll
    for (int j = 0; j < 8; j++)
        t[ty + 8 * j][tx] = src[(size_t)(k0 + ty + 8 * j) * N + n0 + tx];
    __syncthreads();
    const int s  = ty * 32 + tx;
    const int kq = s & 15;          // 0..15 -> k = 4*kq .. 4*kq+3
    const int nb = s >> 4;          // 0..15
#pragma unroll
    for (int j = 0; j < 2; j++) {
        const int n = nb + 16 * j;
        float v0 = t[4 * kq + 0][n];
        float v1 = t[4 * kq + 1][n];
        float v2 = t[4 * kq + 2][n];
        float v3 = t[4 * kq + 3][n];
        bf16 h0, l0, h1, l1, h2, l2, h3, l3;
        split2(v0, h0, l0); split2(v1, h1, l1);
        split2(v2, h2, l2); split2(v3, h3, l3);
        bf4 ph, pl;
        ph.a.x = h0; ph.a.y = h1; ph.b.x = h2; ph.b.y = h3;
        pl.a.x = l0; pl.a.y = l1; pl.b.x = l2; pl.b.y = l3;
        size_t o = (size_t)(n0 + n) * K + k0 + 4 * kq;
        *(bf4*)&dhi[o] = ph;
        *(bf4*)&dlo[o] = pl;
    }
}

__global__ void tconv_qkv_kernel(const float* __restrict__ Wq,
                                 const float* __restrict__ Wk,
                                 const float* __restrict__ Wv,
                                 bf16* __restrict__ dhi, bf16* __restrict__ dlo)
{
    __shared__ float t[64][33];
    const int z = blockIdx.z;
    const int l = z / 48;
    const int rr = z % 48;
    const int which = rr / 16;
    const int h = rr % 16;
    const float* src = (which == 0 ? Wq : which == 1 ? Wk : Wv)
                       + ((size_t)(l * NHEAD + h) * EDIM) * HDIM;
    const int i0 = blockIdx.x * 32;     // 0 or 32
    const int k0 = blockIdx.y * 64;     // 0..960
    const int tx = threadIdx.x, ty = threadIdx.y;
#pragma unroll
    for (int j = 0; j < 8; j++)
        t[ty + 8 * j][tx] = src[(size_t)(k0 + ty + 8 * j) * HDIM + i0 + tx];
    __syncthreads();
    bf16* bh = dhi + (size_t)l * QKVN * EDIM;
    bf16* bl = dlo + (size_t)l * QKVN * EDIM;
    const int s  = ty * 32 + tx;
    const int kq = s & 15;
    const int nb = s >> 4;
#pragma unroll
    for (int j = 0; j < 2; j++) {
        const int ni = nb + 16 * j;
        float v0 = t[4 * kq + 0][ni];
        float v1 = t[4 * kq + 1][ni];
        float v2 = t[4 * kq + 2][ni];
        float v3 = t[4 * kq + 3][ni];
        bf16 h0, l0, h1, l1, h2, l2, h3, l3;
        split2(v0, h0, l0); split2(v1, h1, l1);
        split2(v2, h2, l2); split2(v3, h3, l3);
        bf4 ph, pl;
        ph.a.x = h0; ph.a.y = h1; ph.b.x = h2; ph.b.y = h3;
        pl.a.x = l0; pl.a.y = l1; pl.b.x = l2; pl.b.y = l3;
        int n = which * 1024 + h * 64 + i0 + ni;
        size_t o = (size_t)n * EDIM + k0 + 4 * kq;
        *(bf4*)&bh[o] = ph;
        *(bf4*)&bl[o] = pl;
    }
}

// ---------------- embedding (planes only) ----------------
__global__ void embed_kernel(const int* __restrict__ tokens,
                             const float* __restrict__ emb,
                             const float* __restrict__ pos,
                             bf16* __restrict__ Xh, bf16* __restrict__ Xl)
{
    int idx = blockIdx.x * blockDim.x + threadIdx.x;
    int i  = idx / (EDIM / 4);
    int e4 = idx % (EDIM / 4);
    int tok = tokens[i];
    float4 a = ((const float4*)(emb + (size_t)tok * EDIM))[e4];
    float4 p = ((const float4*)(pos + (size_t)(i & 1) * EDIM))[e4];
    float r[4] = { a.x + p.x, a.y + p.y, a.z + p.z, a.w + p.w };
    bf16 hh[4], ll[4];
#pragma unroll
    for (int j = 0; j < 4; j++) split2(r[j], hh[j], ll[j]);
    bf4 ph, pl;
    ph.a.x = hh[0]; ph.a.y = hh[1]; ph.b.x = hh[2]; ph.b.y = hh[3];
    pl.a.x = ll[0]; pl.a.y = ll[1]; pl.b.x = ll[2]; pl.b.y = ll[3];
    size_t o = (size_t)i * EDIM + e4 * 4;
    *(bf4*)&Xh[o] = ph;
    *(bf4*)&Xl[o] = pl;
}

// ---------------- attention (T=2): one warp per (b,h), no smem ----------------
__global__ void attn_kernel(const float* __restrict__ QKV,
                            bf16* __restrict__ Oh, bf16* __restrict__ Ol)
{
    const int w = blockIdx.x * 8 + (threadIdx.x >> 5);
    const int lane = threadIdx.x & 31;
    const int b = w >> 4;
    const int h = w & 15;
    const size_t base = (size_t)(b * 2) * QKVN + h * HDIM + lane;

    float q0a = QKV[base],               q0b = QKV[base + 32];
    float q1a = QKV[base + QKVN],        q1b = QKV[base + QKVN + 32];
    float k0a = QKV[base + 1024],        k0b = QKV[base + 1056];
    float k1a = QKV[base + QKVN + 1024], k1b = QKV[base + QKVN + 1056];
    float v0a = QKV[base + 2048],        v0b = QKV[base + 2080];
    float v1a = QKV[base + QKVN + 2048], v1b = QKV[base + QKVN + 2080];

    float d00 = q0a * k0a + q0b * k0b;
    float d01 = q0a * k1a + q0b * k1b;
    float d10 = q1a * k0a + q1b * k0b;
    float d11 = q1a * k1a + q1b * k1b;
#pragma unroll
    for (int off = 16; off; off >>= 1) {
        d00 += __shfl_xor_sync(0xffffffffu, d00, off);
        d01 += __shfl_xor_sync(0xffffffffu, d01, off);
        d10 += __shfl_xor_sync(0xffffffffu, d10, off);
        d11 += __shfl_xor_sync(0xffffffffu, d11, off);
    }
    const float scale = 0.125f;
    float s00 = d00 * scale, s01 = d01 * scale;
    float s10 = d10 * scale, s11 = d11 * scale;
    float m0 = fmaxf(s00, s01), m1 = fmaxf(s10, s11);
    float e00 = expf(s00 - m0), e01 = expf(s01 - m0);
    float i0 = 1.0f / (e00 + e01);
    float e10 = expf(s10 - m1), e11 = expf(s11 - m1);
    float i1 = 1.0f / (e10 + e11);
    float p0 = e00 * i0, p1 = e01 * i0, p2 = e10 * i1, p3 = e11 * i1;

    const size_t o0 = (size_t)(b * 2) * EDIM + h * HDIM + lane;
    bf16 hh, ll;
    split2(p0 * v0a + p1 * v1a, hh, ll); Oh[o0] = hh;             Ol[o0] = ll;
    split2(p0 * v0b + p1 * v1b, hh, ll); Oh[o0 + 32] = hh;        Ol[o0 + 32] = ll;
    split2(p2 * v0a + p3 * v1a, hh, ll); Oh[o0 + EDIM] = hh;      Ol[o0 + EDIM] = ll;
    split2(p2 * v0b + p3 * v1b, hh, ll); Oh[o0 + EDIM + 32] = hh; Ol[o0 + EDIM + 32] = ll;
}

// ---------------- 3xBF16 tensor-core GEMM (champion config) ----------------
// RES reads the residual from bf16 hi/lo planes.
#define MMA_BF16(d, a, b0, b1)                                             \
    asm volatile("mma.sync.aligned.m16n8k16.row.col.f32.bf16.bf16.f32 "    \
                 "{%0,%1,%2,%3},{%4,%5,%6,%7},{%8,%9},{%0,%1,%2,%3};"      \
                 : "+f"(d[0]), "+f"(d[1]), "+f"(d[2]), "+f"(d[3])          \
                 : "r"(a[0]), "r"(a[1]), "r"(a[2]), "r"(a[3]),             \
                   "r"(b0), "r"(b1))

#define LDSM_X4(r, a)                                                       \
    asm volatile("ldmatrix.sync.aligned.m8n8.x4.shared.b16 {%0,%1,%2,%3}, [%4];" \
                 : "=r"((r)[0]), "=r"((r)[1]), "=r"((r)[2]), "=r"((r)[3])   \
                 : "r"(a))

__device__ __forceinline__ void cpa16(uint32_t dst, const void* src) {
    asm volatile("cp.async.cg.shared.global [%0], [%1], 16;\n" :: "r"(dst), "l"(src));
}

#define GSTAGE_B 24576
#define GPLANE_B 6144

template<bool BIAS, bool RELU, bool RES, bool WF32, bool WBF>
__global__ void __launch_bounds__(256, 2)
gemm3_kernel(const bf16* __restrict__ Ah_, const bf16* __restrict__ Al_, int lda,
             const bf16* __restrict__ Bh_, const bf16* __restrict__ Bl_,
             const float* __restrict__ bias,
             const bf16* __restrict__ resh, const bf16* __restrict__ resl,
             float* __restrict__ Cf, bf16* __restrict__ Ch, bf16* __restrict__ Cl,
             int N, int K)
{
    extern __shared__ bf16 smem[];
    const int tid  = threadIdx.x;
    const int lane = tid & 31, warp = tid >> 5;
    const int wm = warp >> 2, wn = warp & 3;
    const int g = lane >> 2, t = lane & 3;
    const int rowBase = blockIdx.y * 128;
    const int colBase = blockIdx.x * 128;

    const int lr = tid >> 1;
    const int lc = (tid & 1) * 8;
    const bf16* gAh = Ah_ + (size_t)(rowBase + lr) * lda + lc;
    const bf16* gAl = Al_ + (size_t)(rowBase + lr) * lda + lc;
    const bf16* gBh = Bh_ + (size_t)(colBase + lr) * K + lc;
    const bf16* gBl = Bl_ + (size_t)(colBase + lr) * K + lc;
    const uint32_t sbase = (uint32_t)__cvta_generic_to_shared(smem);
    const uint32_t sw = sbase + (lr * 24 + lc) * 2;

#define LOAD_STAGE(S, KT)                                       \
    do {                                                        \
        uint32_t b_ = sw + (S) * GSTAGE_B;                      \
        int ko_ = (KT) * 16;                                    \
        cpa16(b_,                gAh + ko_);                    \
        cpa16(b_ + GPLANE_B,     gAl + ko_);                    \
        cpa16(b_ + 2 * GPLANE_B, gBh + ko_);                    \
        cpa16(b_ + 3 * GPLANE_B, gBl + ko_);                    \
    } while (0)

    const int lq  = lane & 7;
    const int l8  = (lane >> 3) & 1;
    const int l16 = (lane >> 4) & 1;
    uint32_t offA[4], offB[2];
#pragma unroll
    for (int mi = 0; mi < 4; mi++)
        offA[mi] = ((wm * 64 + mi * 16 + lq + 8 * l8) * 24 + 8 * l16) * 2;
#pragma unroll
    for (int pi = 0; pi < 2; pi++)
        offB[pi] = ((wn * 32 + pi * 16 + lq + 8 * l16) * 24 + 8 * l8) * 2;

    float acc[4][4][4];
#pragma unroll
    for (int i = 0; i < 4; i++)
#pragma unroll
        for (int j = 0; j < 4; j++)
#pragma unroll
            for (int q = 0; q < 4; q++) acc[i][j][q] = 0.0f;

    const int KT = K >> 4;
    LOAD_STAGE(0, 0); asm volatile("cp.async.commit_group;");
    LOAD_STAGE(1, 1); asm volatile("cp.async.commit_group;");

    for (int kt = 0; kt < KT; ++kt) {
        asm volatile("cp.async.wait_group 1;" ::: "memory");
        __syncthreads();
        if (kt + 2 < KT) LOAD_STAGE((kt + 2) % 3, kt + 2);
        asm volatile("cp.async.commit_group;");

        const uint32_t st = sbase + (kt % 3) * GSTAGE_B;
        const uint32_t aH = st;
        const uint32_t aL = st + GPLANE_B;
        const uint32_t bH = st + 2 * GPLANE_B;
        const uint32_t bL = st + 3 * GPLANE_B;

        uint32_t a[4][4];
        uint32_t bh[4][2], bl[4][2];
#pragma unroll
        for (int mi = 0; mi < 4; mi++) LDSM_X4(a[mi], aH + offA[mi]);
        {
            uint32_t r4[4];
            LDSM_X4(r4, bH + offB[0]);
            bh[0][0] = r4[0]; bh[0][1] = r4[1];
            bh[1][0] = r4[2]; bh[1][1] = r4[3];
            LDSM_X4(r4, bH + offB[1]);
            bh[2][0] = r4[0]; bh[2][1] = r4[1];
            bh[3][0] = r4[2]; bh[3][1] = r4[3];
        }

#pragma unroll
        for (int mi = 0; mi < 4; mi++)
#pragma unroll
            for (int ni = 0; ni < 4; ni++)
                MMA_BF16(acc[mi][ni], a[mi], bh[ni][0], bh[ni][1]);

        {
            uint32_t r4[4];
            LDSM_X4(r4, bL + offB[0]);
            bl[0][0] = r4[0]; bl[0][1] = r4[1];
            bl[1][0] = r4[2]; bl[1][1] = r4[3];
            LDSM_X4(r4, bL + offB[1]);
            bl[2][0] = r4[0]; bl[2][1] = r4[1];
            bl[3][0] = r4[2]; bl[3][1] = r4[3];
        }

#pragma unroll
        for (int mi = 0; mi < 4; mi++)
#pragma unroll
            for (int ni = 0; ni < 4; ni++)
                MMA_BF16(acc[mi][ni], a[mi], bl[ni][0], bl[ni][1]);

#pragma unroll
        for (int mi = 0; mi < 4; mi++) LDSM_X4(a[mi], aL + offA[mi]);

#pragma unroll
        for (int mi = 0; mi < 4; mi++)
#pragma unroll
            for (int ni = 0; ni < 4; ni++)
                MMA_BF16(acc[mi][ni], a[mi], bh[ni][0], bh[ni][1]);
    }
#undef LOAD_STAGE

    // epilogue
#pragma unroll
    for (int ni = 0; ni < 4; ni++) {
        const int cb = colBase + wn * 32 + ni * 8 + 2 * t;
        float b0 = 0.0f, b1 = 0.0f;
        if (BIAS) { b0 = bias[cb]; b1 = bias[cb + 1]; }
#pragma unroll
        for (int mi = 0; mi < 4; mi++) {
#pragma unroll
            for (int hh = 0; hh < 2; hh++) {
                const int rr = rowBase + wm * 64 + mi * 16 + g + hh * 8;
                float v0 = acc[mi][ni][hh * 2 + 0];
                float v1 = acc[mi][ni][hh * 2 + 1];
                if (BIAS) { v0 += b0; v1 += b1; }
                if (RELU) { v0 = fmaxf(v0, 0.0f); v1 = fmaxf(v1, 0.0f); }
                if (RES) {
                    const __nv_bfloat162 rh = *(const __nv_bfloat162*)&resh[(size_t)rr * N + cb];
                    const __nv_bfloat162 rl = *(const __nv_bfloat162*)&resl[(size_t)rr * N + cb];
                    v0 += __bfloat162float(rh.x) + __bfloat162float(rl.x);
                    v1 += __bfloat162float(rh.y) + __bfloat162float(rl.y);
                }
                if (WF32) {
                    float2 ov; ov.x = v0; ov.y = v1;
                    *(float2*)&Cf[(size_t)rr * N + cb] = ov;
                }
                if (WBF) {
                    bf16 h0, l0, h1, l1;
                    split2(v0, h0, l0); split2(v1, h1, l1);
                    __nv_bfloat162 ph; ph.x = h0; ph.y = h1;
                    __nv_bfloat162 pl; pl.x = l0; pl.y = l1;
                    *(__nv_bfloat162*)&Ch[(size_t)rr * N + cb] = ph;
                    *(__nv_bfloat162*)&Cl[(size_t)rr * N + cb] = pl;
                }
            }
        }
    }
}

// ---------------- launcher ----------------
extern "C" void kernel_launch(void* const* d_in, const int* in_sizes, int n_in,
                              void* d_out, int out_size)
{
    (void)in_sizes; (void)n_in; (void)out_size;
    const int*   tokens  = (const int*)  d_in[0];
    const float* emb     = (const float*)d_in[1];
    const float* pos     = (const float*)d_in[2];
    const float* Wq      = (const float*)d_in[3];
    const float* Wk      = (const float*)d_in[4];
    const float* Wv      = (const float*)d_in[5];
    const float* Wo      = (const float*)d_in[6];
    const float* W1      = (const float*)d_in[7];
    const float* b1      = (const float*)d_in[8];
    const float* W2      = (const float*)d_in[9];
    const float* b2      = (const float*)d_in[10];
    const float* unembed = (const float*)d_in[11];
    float* out = (float*)d_out;

    bf16 *Wqkvh, *Wqkvl, *Woh, *Wol, *W1h, *W1l, *W2h, *W2l, *Ueh, *Uel;
    float *QKV;
    bf16 *Xh, *Xl, *X2h, *X2l, *Oh, *Ol, *H1h, *H1l;
    cudaGetSymbolAddress((void**)&Wqkvh, g_Wqkv_h);
    cudaGetSymbolAddress((void**)&Wqkvl, g_Wqkv_l);
    cudaGetSymbolAddress((void**)&Woh,   g_Wo_h);
    cudaGetSymbolAddress((void**)&Wol,   g_Wo_l);
    cudaGetSymbolAddress((void**)&W1h,   g_W1_h);
    cudaGetSymbolAddress((void**)&W1l,   g_W1_l);
    cudaGetSymbolAddress((void**)&W2h,   g_W2_h);
    cudaGetSymbolAddress((void**)&W2l,   g_W2_l);
    cudaGetSymbolAddress((void**)&Ueh,   g_Ue_h);
    cudaGetSymbolAddress((void**)&Uel,   g_Ue_l);
    cudaGetSymbolAddress((void**)&QKV, g_QKV);
    cudaGetSymbolAddress((void**)&Xh,  g_Xh);
    cudaGetSymbolAddress((void**)&Xl,  g_Xl);
    cudaGetSymbolAddress((void**)&X2h, g_X2h);
    cudaGetSymbolAddress((void**)&X2l, g_X2l);
    cudaGetSymbolAddress((void**)&Oh,  g_Oh);
    cudaGetSymbolAddress((void**)&Ol,  g_Ol);
    cudaGetSymbolAddress((void**)&H1h, g_H1h);
    cudaGetSymbolAddress((void**)&H1l, g_H1l);

    const int SMEM = 3 * GSTAGE_B;
    cudaFuncSetAttribute(gemm3_kernel<false, false, false, true,  false>,
                         cudaFuncAttributeMaxDynamicSharedMemorySize, SMEM);
    cudaFuncSetAttribute(gemm3_kernel<false, false, true,  false, true >,
                         cudaFuncAttributeMaxDynamicSharedMemorySize, SMEM);
    cudaFuncSetAttribute(gemm3_kernel<true,  true,  false, false, true >,
                         cudaFuncAttributeMaxDynamicSharedMemorySize, SMEM);
    cudaFuncSetAttribute(gemm3_kernel<true,  true,  true,  false, true >,
                         cudaFuncAttributeMaxDynamicSharedMemorySize, SMEM);

    // ---- weight prep (transpose + bf16 split) ----
    {
        dim3 b(32, 8);
        tconv_qkv_kernel<<<dim3(2, 16, NLAYER * 48), b>>>(Wq, Wk, Wv, Wqkvh, Wqkvl);
        tconv_kernel<<<dim3(32, 16, NLAYER), b>>>(Wo, Woh, Wol, EDIM, EDIM);
        tconv_kernel<<<dim3(128, 16, NLAYER), b>>>(W1, W1h, W1l, EDIM, HID);
        tconv_kernel<<<dim3(32, 64, NLAYER), b>>>(W2, W2h, W2l, HID, EDIM);
        tconv_kernel<<<dim3(1000, 16, 1), b>>>(unembed, Ueh, Uel, EDIM, VOC);
    }

    embed_kernel<<<(NTOK * EDIM / 4) / 256, 256>>>(tokens, emb, pos, Xh, Xl);

    const dim3 blk(256);
    for (int l = 0; l < NLAYER; l++) {
        const bf16* wqh = Wqkvh + (size_t)l * QKVN * EDIM;
        const bf16* wql = Wqkvl + (size_t)l * QKVN * EDIM;
        const bf16* woh = Woh + (size_t)l * EDIM * EDIM;
        const bf16* wol = Wol + (size_t)l * EDIM * EDIM;
        const bf16* w1h = W1h + (size_t)l * HID * EDIM;
        const bf16* w1l = W1l + (size_t)l * HID * EDIM;
        const bf16* w2h = W2h + (size_t)l * EDIM * HID;
        const bf16* w2l = W2l + (size_t)l * EDIM * HID;
        const float* b1l = b1 + (size_t)l * HID;
        const float* b2l = b2 + (size_t)l * EDIM;

        // QKV = X @ Wqkv            [4096, 3072] -> f32 (attention input)
        gemm3_kernel<false, false, false, true, false>
            <<<dim3(QKVN / 128, NTOK / 128), blk, SMEM>>>(
            Xh, Xl, EDIM, wqh, wql, nullptr, nullptr, nullptr,
            QKV, nullptr, nullptr, QKVN, EDIM);

        attn_kernel<<<BATCH * NHEAD / 8, 256>>>(QKV, Oh, Ol);

        // X2 = O @ Wo + X           [4096, 1024]  (planes only; residual from X planes)
        gemm3_kernel<false, false, true, false, true>
            <<<dim3(EDIM / 128, NTOK / 128), blk, SMEM>>>(
            Oh, Ol, EDIM, woh, wol, nullptr, Xh, Xl,
            nullptr, X2h, X2l, EDIM, EDIM);

        // H1 = relu(X2 @ W1 + b1)   [4096, 4096]  (planes only)
        gemm3_kernel<true, true, false, false, true>
            <<<dim3(HID / 128, NTOK / 128), blk, SMEM>>>(
            X2h, X2l, EDIM, w1h, w1l, b1l, nullptr, nullptr,
            nullptr, H1h, H1l, HID, EDIM);

        // X = relu(H1 @ W2 + b2) + X2   [4096, 1024]  (planes only; residual X2 planes)
        gemm3_kernel<true, true, true, false, true>
            <<<dim3(EDIM / 128, NTOK / 128), blk, SMEM>>>(
            H1h, H1l, HID, w2h, w2l, b2l, X2h, X2l,
            nullptr, Xh, Xl, EDIM, HID);
    }

    // logits = X[:, odd rows, :] @ unembed    [2048, 32000] -> f32 out
    gemm3_kernel<false, false, false, true, false>
        <<<dim3(VOC / 128, BATCH / 128), blk, SMEM>>>(
        Xh + EDIM, Xl + EDIM, 2 * EDIM, Ueh, Uel, nullptr, nullptr, nullptr,
        out, nullptr, nullptr, VOC, EDIM);
}